// round 4
// baseline (speedup 1.0000x reference)
#include <cuda_runtime.h>
#include <cuda_bf16.h>
#include <math.h>
#include <cstdint>

#if defined(__CUDA_ARCH_SPECIFIC__) || defined(__CUDA_ARCH_FEAT_SM103_ALL)
#define HAS_TCGEN05 1
#else
#define HAS_TCGEN05 0
#endif

// ---------------------------------------------------------------------------
// Scratch buffers
// ---------------------------------------------------------------------------
__device__ float g_s0[128 * 128 * 256];
__device__ float g_s1[256 * 64 * 128];
__device__ float g_p0[128 * 12 * 128 * 256];
__device__ float g_p1[256 * 6 * 64 * 128];
__device__ float g_feats[512 * 4 * 32 * 64];
__device__ float g_yn[512 * 8192];
__device__ float g_qkv[8192 * 1536];
__device__ float g_at[8192 * 512];
__device__ int2  g_dec[8192];
__device__ int   g_ndelta[256];
__device__ int   g_npack[256];

// ---------------------------------------------------------------------------
// PTX helpers (only expanded inside HAS_TCGEN05 code)
// ---------------------------------------------------------------------------
__device__ __forceinline__ uint32_t smem_u32(const void* p) {
    uint32_t a;
    asm("{ .reg .u64 t; cvta.to.shared.u64 t, %1; cvt.u32.u64 %0, t; }"
        : "=r"(a) : "l"(p));
    return a;
}
#if HAS_TCGEN05
__device__ __forceinline__ uint32_t elect_one() {
    uint32_t pred;
    asm volatile("{ .reg .pred p; elect.sync _|p, 0xFFFFFFFF; selp.b32 %0, 1, 0, p; }"
                 : "=r"(pred));
    return pred;
}
#define TCGEN05_ALLOC(a, n) \
    asm volatile("tcgen05.alloc.cta_group::1.sync.aligned.shared::cta.b32 [%0], %1;" \
                 :: "r"((uint32_t)(a)), "r"((uint32_t)(n)) : "memory")
#define TCGEN05_DEALLOC(t, n) \
    asm volatile("tcgen05.dealloc.cta_group::1.sync.aligned.b32 %0, %1;" :: "r"(t), "r"(n))
#define TCGEN05_RELINQ() \
    asm volatile("tcgen05.relinquish_alloc_permit.cta_group::1.sync.aligned;")
#define TCGEN05_COMMIT(m) \
    asm volatile("tcgen05.commit.cta_group::1.mbarrier::arrive::one.shared::cluster.b64 [%0];" \
                 :: "r"((uint32_t)(m)) : "memory")
#define TCGEN05_FENCE_AFTER() \
    asm volatile("tcgen05.fence::after_thread_sync;" ::: "memory")
#define TCGEN05_FENCE_BEFORE() \
    asm volatile("tcgen05.fence::before_thread_sync;" ::: "memory")
#define TCGEN05_WAIT_LD() asm volatile("tcgen05.wait::ld.sync.aligned;" ::: "memory")
#define FENCE_PROXY_ASYNC() asm volatile("fence.proxy.async.shared::cta;" ::: "memory")
#define MBARRIER_INIT(m, c) \
    asm volatile("mbarrier.init.shared.b64 [%0], %1;" :: "r"((uint32_t)(m)), "r"((uint32_t)(c)) : "memory")
#define MBARRIER_INVAL(m) \
    asm volatile("mbarrier.inval.shared.b64 [%0];" :: "r"((uint32_t)(m)) : "memory")
#define MBARRIER_WAIT_PARITY(m, ph) do {                                           \
    uint32_t _m = (uint32_t)(m), _p = (uint32_t)(ph), _d;                          \
    asm volatile("{ .reg .pred p; mbarrier.try_wait.parity.acquire.cta.shared::cta.b64 p, [%1], %2;" \
                 " selp.b32 %0, 1, 0, p; }" : "=r"(_d) : "r"(_m), "r"(_p) : "memory"); \
    if (!_d) {                                                                     \
        asm volatile("{ .reg .pred P1; WL_%=: mbarrier.try_wait.parity.acquire.cta.shared::cta.b64 P1, [%0], %1, 0x989680;" \
                     " @P1 bra.uni WD_%=; bra.uni WL_%=; WD_%=: }"                 \
                     :: "r"(_m), "r"(_p) : "memory");                              \
    }                                                                              \
} while (0)
#define TCGEN05_LD_X32(r, a)                                                       \
    asm volatile("tcgen05.ld.sync.aligned.32x32b.x32.b32 "                         \
        "{%0, %1, %2, %3, %4, %5, %6, %7, %8, %9, %10, %11, %12, %13, %14, %15, "  \
        " %16, %17, %18, %19, %20, %21, %22, %23, %24, %25, %26, %27, %28, %29, %30, %31}, [%32];" \
        : "=r"((r)[0]), "=r"((r)[1]), "=r"((r)[2]), "=r"((r)[3]),                  \
          "=r"((r)[4]), "=r"((r)[5]), "=r"((r)[6]), "=r"((r)[7]),                  \
          "=r"((r)[8]), "=r"((r)[9]), "=r"((r)[10]), "=r"((r)[11]),                \
          "=r"((r)[12]), "=r"((r)[13]), "=r"((r)[14]), "=r"((r)[15]),              \
          "=r"((r)[16]), "=r"((r)[17]), "=r"((r)[18]), "=r"((r)[19]),              \
          "=r"((r)[20]), "=r"((r)[21]), "=r"((r)[22]), "=r"((r)[23]),              \
          "=r"((r)[24]), "=r"((r)[25]), "=r"((r)[26]), "=r"((r)[27]),              \
          "=r"((r)[28]), "=r"((r)[29]), "=r"((r)[30]), "=r"((r)[31])               \
        : "r"(a))

static constexpr uint64_t SMEM_DESC_BASE_SW128 =
    (uint64_t(2) << 61) | (uint64_t(1) << 46) | (uint64_t(64) << 32) | (uint64_t(1) << 16);
__device__ __forceinline__ uint64_t make_desc(uint32_t addr) {
    return SMEM_DESC_BASE_SW128 | ((uint64_t)(addr >> 4) & 0x3FFF);
}
__device__ __forceinline__ void mma_f16_ss(uint32_t d, uint64_t ad, uint64_t bd,
                                           uint32_t idesc, uint32_t en) {
    asm volatile(
        "{ .reg .pred p; setp.ne.u32 p, %5, 0;\n\t"
        "tcgen05.mma.cta_group::1.kind::f16 [%0], %1, %2, %3, {%4, %4, %4, %4}, p; }"
        :: "r"(d), "l"(ad), "l"(bd), "r"(idesc), "r"(0u), "r"(en) : "memory");
}
// idesc: F32 out, BF16 x BF16, N=128, M=128
static constexpr uint32_t CONV_IDESC =
    (1u << 4) | (1u << 7) | (1u << 10) | ((128u / 8) << 17) | ((128u / 16) << 24);
#endif // HAS_TCGEN05

__device__ __forceinline__ float gelu_tanh(float x) {
    float x3 = x * x * x;
    float t = tanhf(0.7978845608028654f * (x + 0.044715f * x3));
    return 0.5f * x * (1.0f + t);
}

// ---------------------------------------------------------------------------
// Decode-table init kernels
// ---------------------------------------------------------------------------
__global__ void conv_decode_kernel(int K, int Kpad, int KV, int KHW, int KW,
                                   int D, int H, int W) {
    int k = blockIdx.x * 256 + threadIdx.x;
    if (k >= Kpad) return;
    if (k < K) {
        int ci = k / KV; int tap = k - ci * KV;
        int kd = tap / KHW; int t2 = tap - kd * KHW;
        int kh = t2 / KW; int kw = t2 - kh * KW;
        g_dec[k] = make_int2(((ci * D + kd) * H + kh) * W + kw,
                             (kd << 20) | (kh << 10) | kw);
    } else {
        g_dec[k] = make_int2(0, 1023 << 20);
    }
}

__global__ void natt_table_kernel() {
    int nb = threadIdx.x;
    if (nb < 245) {
        int od = nb / 49; int r = nb - od * 49;
        int oh = r / 7;   int ow = r - oh * 7;
        g_ndelta[nb] = (od - 2) * 2048 + (oh - 3) * 64 + (ow - 3);
        g_npack[nb]  = (od << 16) | (oh << 8) | ow;
    }
}

// ---------------------------------------------------------------------------
// Conv kernel: tcgen05 path (sm_103a) or FFMA fallback (other targets).
// Tile M=128(Cout) x N=128(vox). Grid: (Nvox/128, Cout/128). Block 256.
// ---------------------------------------------------------------------------
struct ConvParams {
    const float* x; const float* w; const float* bias; float* out;
    int D, H, W;
    int Hout, Wout;
    int sd, sh, sw, pd, ph, pw;
    int K, Kpad;             // Kpad multiple of 64
    int outStrideC, outOffset;
    int gelu;
};

#define CONV_SMEM_BYTES (1024 + 8 * 16384 + 64)

__global__ __launch_bounds__(256) void conv_mma_kernel(ConvParams p) {
    extern __shared__ char smem_raw[];
    char* smem_al = (char*)(((uintptr_t)smem_raw + 1023) & ~(uintptr_t)1023);

    const int tid = threadIdx.x;
    const int bn = blockIdx.x, bm = blockIdx.y;
    const int m_base = bm * 128;
    const int HWo = p.Hout * p.Wout;

#if HAS_TCGEN05
    const uint32_t sb = smem_u32(smem_al);
    const uint32_t mbar = sb + 131072;
    const uint32_t tmem_slot = sb + 131080;
    const int wid = tid >> 5;
    const int lane = tid & 31;

    if (wid == 0) {
        TCGEN05_ALLOC(tmem_slot, 128);
        TCGEN05_RELINQ();
    }
    if (tid == 0) MBARRIER_INIT(mbar, 1);
    __syncthreads();
    uint32_t tmem;
    asm volatile("ld.shared.b32 %0, [%1];" : "=r"(tmem) : "r"(tmem_slot));

    const int r = tid >> 1;
    const int h = tid & 1;
    const int k0 = h * 32;
    const int n = bn * 128 + r;
    const int od = n / HWo; int rr2 = n - od * HWo;
    const int oh = rr2 / p.Wout; const int ow = rr2 - oh * p.Wout;
    const int id0 = od * p.sd - p.pd;
    const int ih0 = oh * p.sh - p.ph;
    const int iw0 = ow * p.sw - p.pw;
    const int gbase = (id0 * p.H + ih0) * p.W + iw0;
    const float* wrow = p.w + (size_t)(m_base + r) * p.K;
    const int rowoff = r * 128;

    auto tile_ptr = [&](int st, int which) -> char* {
        return smem_al + st * 65536 + which * 16384;
    };
    const int NC = p.Kpad / 64;

    auto fill = [&](int st, int kt) {
        char* Ahi = tile_ptr(st, 0);
        char* Alo = tile_ptr(st, 1);
        char* Bhi = tile_ptr(st, 2);
        char* Blo = tile_ptr(st, 3);
#pragma unroll
        for (int i = 0; i < 16; i++) {
            int kk = k0 + 2 * i;
            int k = kt + kk;
            float a0 = (k < p.K) ? wrow[k] : 0.f;
            float a1 = (k + 1 < p.K) ? wrow[k + 1] : 0.f;
            float b0 = 0.f, b1 = 0.f;
            {
                int2 dv = __ldg(&g_dec[k]);
                int kd = dv.y >> 20, kh = (dv.y >> 10) & 1023, kw = dv.y & 1023;
                if ((unsigned)(id0 + kd) < (unsigned)p.D &&
                    (unsigned)(ih0 + kh) < (unsigned)p.H &&
                    (unsigned)(iw0 + kw) < (unsigned)p.W)
                    b0 = p.x[gbase + dv.x];
            }
            {
                int2 dv = __ldg(&g_dec[k + 1]);
                int kd = dv.y >> 20, kh = (dv.y >> 10) & 1023, kw = dv.y & 1023;
                if ((unsigned)(id0 + kd) < (unsigned)p.D &&
                    (unsigned)(ih0 + kh) < (unsigned)p.H &&
                    (unsigned)(iw0 + kw) < (unsigned)p.W)
                    b1 = p.x[gbase + dv.x];
            }
            uint32_t off = rowoff + kk * 2;
            uint32_t sw = off ^ ((off >> 3) & 0x70);
            __nv_bfloat16 ah0 = __float2bfloat16(a0);
            __nv_bfloat16 ah1 = __float2bfloat16(a1);
            __nv_bfloat16 al0 = __float2bfloat16(a0 - __bfloat162float(ah0));
            __nv_bfloat16 al1 = __float2bfloat16(a1 - __bfloat162float(ah1));
            __nv_bfloat16 bh0 = __float2bfloat16(b0);
            __nv_bfloat16 bh1 = __float2bfloat16(b1);
            __nv_bfloat16 bl0 = __float2bfloat16(b0 - __bfloat162float(bh0));
            __nv_bfloat16 bl1 = __float2bfloat16(b1 - __bfloat162float(bh1));
            __nv_bfloat162 pa_hi{ah0, ah1}, pa_lo{al0, al1};
            __nv_bfloat162 pb_hi{bh0, bh1}, pb_lo{bl0, bl1};
            *reinterpret_cast<uint32_t*>(Ahi + sw) = *reinterpret_cast<uint32_t*>(&pa_hi);
            *reinterpret_cast<uint32_t*>(Alo + sw) = *reinterpret_cast<uint32_t*>(&pa_lo);
            *reinterpret_cast<uint32_t*>(Bhi + sw) = *reinterpret_cast<uint32_t*>(&pb_hi);
            *reinterpret_cast<uint32_t*>(Blo + sw) = *reinterpret_cast<uint32_t*>(&pb_lo);
        }
    };

    fill(0, 0);
    FENCE_PROXY_ASYNC();
    __syncthreads();

    int wpar = 0;
    uint32_t first = 0;

    for (int kc = 0; kc < NC; kc++) {
        int st = kc & 1;
        if (wid == 0 && elect_one()) {
            uint64_t dAh = make_desc(sb + st * 65536 + 0 * 16384);
            uint64_t dAl = make_desc(sb + st * 65536 + 1 * 16384);
            uint64_t dBh = make_desc(sb + st * 65536 + 2 * 16384);
            uint64_t dBl = make_desc(sb + st * 65536 + 3 * 16384);
#pragma unroll
            for (int s = 0; s < 4; s++) {
                uint64_t o = s * 2;
                mma_f16_ss(tmem, dAh + o, dBh + o, CONV_IDESC, first); first = 1;
                mma_f16_ss(tmem, dAh + o, dBl + o, CONV_IDESC, 1);
                mma_f16_ss(tmem, dAl + o, dBh + o, CONV_IDESC, 1);
            }
            TCGEN05_COMMIT(mbar);
        }
        if (kc + 1 < NC) {
            if (kc >= 1) { MBARRIER_WAIT_PARITY(mbar, wpar & 1); wpar++; }
            fill((kc + 1) & 1, (kc + 1) * 64);
            FENCE_PROXY_ASYNC();
            __syncthreads();
        }
    }
    while (wpar < NC) { MBARRIER_WAIT_PARITY(mbar, wpar & 1); wpar++; }
    TCGEN05_FENCE_AFTER();

    if (wid < 4) {
        const int m = m_base + wid * 32 + lane;
        const float bv = p.bias[m];
        float* orow = p.out + (size_t)m * p.outStrideC + p.outOffset + bn * 128;
#pragma unroll
        for (int c0 = 0; c0 < 128; c0 += 32) {
            uint32_t dr[32];
            TCGEN05_LD_X32(dr, tmem + c0);
            TCGEN05_WAIT_LD();
#pragma unroll
            for (int q = 0; q < 8; q++) {
                float4 o;
                o.x = __uint_as_float(dr[q * 4 + 0]) + bv;
                o.y = __uint_as_float(dr[q * 4 + 1]) + bv;
                o.z = __uint_as_float(dr[q * 4 + 2]) + bv;
                o.w = __uint_as_float(dr[q * 4 + 3]) + bv;
                if (p.gelu) {
                    o.x = gelu_tanh(o.x); o.y = gelu_tanh(o.y);
                    o.z = gelu_tanh(o.z); o.w = gelu_tanh(o.w);
                }
                *reinterpret_cast<float4*>(orow + c0 + q * 4) = o;
            }
        }
        TCGEN05_FENCE_BEFORE();
    }
    __syncthreads();
    if (tid == 0) MBARRIER_INVAL(mbar);
    if (wid == 0) TCGEN05_DEALLOC(tmem, 128);

#else  // ------------------- FFMA fallback (non sm_103a targets) -------------
    float (*As)[128] = reinterpret_cast<float(*)[128]>(smem_al);
    float (*Bs)[128] = reinterpret_cast<float(*)[128]>(smem_al + 16 * 128 * 4);

    const int tx = tid & 15, ty = tid >> 4;
    // A-load mapping: row lm, k-half
    const int lm = tid >> 1;
    const int ah = (tid & 1) * 8;
    // B-load mapping
    const int ln = tid & 127, kg = tid >> 7;

    const int n = bn * 128 + ln;
    const int od = n / HWo; int rr2 = n - od * HWo;
    const int oh = rr2 / p.Wout; const int ow = rr2 - oh * p.Wout;
    const int id0 = od * p.sd - p.pd;
    const int ih0 = oh * p.sh - p.ph;
    const int iw0 = ow * p.sw - p.pw;
    const int gbase = (id0 * p.H + ih0) * p.W + iw0;
    const float* wrow = p.w + (size_t)(m_base + lm) * p.K;

    float acc[8][8];
#pragma unroll
    for (int i = 0; i < 8; i++)
#pragma unroll
        for (int j = 0; j < 8; j++) acc[i][j] = 0.f;

    for (int kt = 0; kt < p.Kpad; kt += 16) {
#pragma unroll
        for (int i = 0; i < 8; i++) {
            int k = kt + ah + i;
            As[ah + i][lm] = (k < p.K) ? wrow[k] : 0.f;
        }
#pragma unroll
        for (int i = 0; i < 8; i++) {
            int kk = kg * 8 + i;
            int2 dv = __ldg(&g_dec[kt + kk]);
            int kd = dv.y >> 20, kh = (dv.y >> 10) & 1023, kw = dv.y & 1023;
            float v = 0.f;
            if ((unsigned)(id0 + kd) < (unsigned)p.D &&
                (unsigned)(ih0 + kh) < (unsigned)p.H &&
                (unsigned)(iw0 + kw) < (unsigned)p.W)
                v = p.x[gbase + dv.x];
            Bs[kk][ln] = v;
        }
        __syncthreads();
#pragma unroll
        for (int kq = 0; kq < 16; kq++) {
            float4 a0 = *reinterpret_cast<const float4*>(&As[kq][ty * 8]);
            float4 a1 = *reinterpret_cast<const float4*>(&As[kq][ty * 8 + 4]);
            float4 b0 = *reinterpret_cast<const float4*>(&Bs[kq][tx * 8]);
            float4 b1 = *reinterpret_cast<const float4*>(&Bs[kq][tx * 8 + 4]);
            float av[8] = {a0.x, a0.y, a0.z, a0.w, a1.x, a1.y, a1.z, a1.w};
            float bv[8] = {b0.x, b0.y, b0.z, b0.w, b1.x, b1.y, b1.z, b1.w};
#pragma unroll
            for (int i = 0; i < 8; i++)
#pragma unroll
                for (int j = 0; j < 8; j++)
                    acc[i][j] = fmaf(av[i], bv[j], acc[i][j]);
        }
        __syncthreads();
    }

#pragma unroll
    for (int i = 0; i < 8; i++) {
        int m = m_base + ty * 8 + i;
        float bvl = p.bias[m];
        float* orow = p.out + (size_t)m * p.outStrideC + p.outOffset + bn * 128;
        float4 o0, o1;
        o0.x = acc[i][0] + bvl; o0.y = acc[i][1] + bvl;
        o0.z = acc[i][2] + bvl; o0.w = acc[i][3] + bvl;
        o1.x = acc[i][4] + bvl; o1.y = acc[i][5] + bvl;
        o1.z = acc[i][6] + bvl; o1.w = acc[i][7] + bvl;
        if (p.gelu) {
            o0.x = gelu_tanh(o0.x); o0.y = gelu_tanh(o0.y);
            o0.z = gelu_tanh(o0.z); o0.w = gelu_tanh(o0.w);
            o1.x = gelu_tanh(o1.x); o1.y = gelu_tanh(o1.y);
            o1.z = gelu_tanh(o1.z); o1.w = gelu_tanh(o1.w);
        }
        *reinterpret_cast<float4*>(orow + tx * 8) = o0;
        *reinterpret_cast<float4*>(orow + tx * 8 + 4) = o1;
    }
#endif
}

// ---------------------------------------------------------------------------
// Token GEMM (fp32, unchanged)
// ---------------------------------------------------------------------------
template <int ALAYOUT, int OUTMODE>
__global__ __launch_bounds__(256) void tok_gemm_kernel(
    const float* __restrict__ A, const float* __restrict__ B,
    const float* __restrict__ bias, float* __restrict__ C,
    int T, int J, int K) {
    __shared__ __align__(16) float As[16][64];
    __shared__ __align__(16) float Bs[16][128];

    const int tid = threadIdx.x;
    const int bj = blockIdx.x, bt = blockIdx.y;
    const int tx = tid & 15, ty = tid >> 4;
    const int lj = tid & 127, kgrp2 = tid >> 7;

    float acc[4][8];
#pragma unroll
    for (int i = 0; i < 4; i++)
#pragma unroll
        for (int j = 0; j < 8; j++) acc[i][j] = 0.f;

    for (int kt = 0; kt < K; kt += 16) {
        if (ALAYOUT == 0) {
            const int lt = tid & 63, kg = tid >> 6;
#pragma unroll
            for (int r = 0; r < 4; r++) {
                int kk = kg * 4 + r;
                As[kk][lt] = A[(size_t)(kt + kk) * T + bt * 64 + lt];
            }
        } else {
            const int lt = tid >> 2, lk4 = (tid & 3) << 2;
            float4 v = *reinterpret_cast<const float4*>(
                A + (size_t)(bt * 64 + lt) * K + kt + lk4);
            As[lk4 + 0][lt] = v.x; As[lk4 + 1][lt] = v.y;
            As[lk4 + 2][lt] = v.z; As[lk4 + 3][lt] = v.w;
        }
#pragma unroll
        for (int r = 0; r < 8; r++) {
            int kk = kgrp2 * 8 + r;
            Bs[kk][lj] = B[(size_t)(kt + kk) * J + bj * 128 + lj];
        }
        __syncthreads();
#pragma unroll
        for (int kq = 0; kq < 16; kq++) {
            float4 a  = *reinterpret_cast<const float4*>(&As[kq][ty * 4]);
            float4 b0 = *reinterpret_cast<const float4*>(&Bs[kq][tx * 4]);
            float4 b1 = *reinterpret_cast<const float4*>(&Bs[kq][64 + tx * 4]);
            float av[4] = {a.x, a.y, a.z, a.w};
            float bv[8] = {b0.x, b0.y, b0.z, b0.w, b1.x, b1.y, b1.z, b1.w};
#pragma unroll
            for (int i = 0; i < 4; i++)
#pragma unroll
                for (int j = 0; j < 8; j++)
                    acc[i][j] = fmaf(av[i], bv[j], acc[i][j]);
        }
        __syncthreads();
    }

    if (OUTMODE == 0) {
#pragma unroll
        for (int i = 0; i < 4; i++) {
            int t = bt * 64 + ty * 4 + i;
            int j0 = bj * 128 + tx * 4;
            int j1 = j0 + 64;
            float4 o0, o1;
            o0.x = acc[i][0] + bias[j0 + 0]; o0.y = acc[i][1] + bias[j0 + 1];
            o0.z = acc[i][2] + bias[j0 + 2]; o0.w = acc[i][3] + bias[j0 + 3];
            o1.x = acc[i][4] + bias[j1 + 0]; o1.y = acc[i][5] + bias[j1 + 1];
            o1.z = acc[i][6] + bias[j1 + 2]; o1.w = acc[i][7] + bias[j1 + 3];
            *reinterpret_cast<float4*>(C + (size_t)t * J + j0) = o0;
            *reinterpret_cast<float4*>(C + (size_t)t * J + j1) = o1;
        }
    } else {
        int t0 = bt * 64 + ty * 4;
#pragma unroll
        for (int j = 0; j < 4; j++) {
            int jj = bj * 128 + tx * 4 + j;
            float bvl = bias[jj];
            float4* cp = reinterpret_cast<float4*>(C + (size_t)jj * T + t0);
            float4 o = *cp;
            o.x += acc[0][j] + bvl; o.y += acc[1][j] + bvl;
            o.z += acc[2][j] + bvl; o.w += acc[3][j] + bvl;
            *cp = o;
        }
#pragma unroll
        for (int j = 0; j < 4; j++) {
            int jj = bj * 128 + 64 + tx * 4 + j;
            float bvl = bias[jj];
            float4* cp = reinterpret_cast<float4*>(C + (size_t)jj * T + t0);
            float4 o = *cp;
            o.x += acc[0][4 + j] + bvl; o.y += acc[1][4 + j] + bvl;
            o.z += acc[2][4 + j] + bvl; o.w += acc[3][4 + j] + bvl;
            *cp = o;
        }
    }
}

// ---------------------------------------------------------------------------
// LayerNorm (unchanged)
// ---------------------------------------------------------------------------
__global__ __launch_bounds__(256) void layernorm_kernel(
    const float* __restrict__ x, const float* __restrict__ g,
    const float* __restrict__ b, float* __restrict__ y, int T) {
    const int tx = threadIdx.x;
    const int ty = threadIdx.y;
    const int t = blockIdx.x * 32 + tx;

    float s = 0.f, ss = 0.f;
#pragma unroll
    for (int i = 0; i < 64; i++) {
        int c = ty * 64 + i;
        float v = x[(size_t)c * T + t];
        s += v; ss += v * v;
    }
    __shared__ float shs[8][32], shss[8][32];
    __shared__ float smu[32], srs[32];
    shs[ty][tx] = s; shss[ty][tx] = ss;
    __syncthreads();
    if (ty == 0) {
        float S = 0.f, SS = 0.f;
#pragma unroll
        for (int j = 0; j < 8; j++) { S += shs[j][tx]; SS += shss[j][tx]; }
        float mu = S * (1.f / 512.f);
        float var = SS * (1.f / 512.f) - mu * mu;
        smu[tx] = mu;
        srs[tx] = rsqrtf(var + 1e-5f);
    }
    __syncthreads();
    float mu = smu[tx], rs = srs[tx];
#pragma unroll
    for (int i = 0; i < 64; i++) {
        int c = ty * 64 + i;
        float v = x[(size_t)c * T + t];
        y[(size_t)c * T + t] = (v - mu) * rs * g[c] + b[c];
    }
}

// ---------------------------------------------------------------------------
// Neighborhood attention (unchanged)
// ---------------------------------------------------------------------------
__global__ __launch_bounds__(256) void natt_kernel(
    const float* __restrict__ qkv, float* __restrict__ at) {
    const int warp = threadIdx.x >> 5;
    const int lane = threadIdx.x & 31;
    const int t = blockIdx.x * 8 + warp;
    const int head = blockIdx.y;
    const int d = t >> 11;
    const int hh = (t >> 6) & 31;
    const int ww = t & 63;

    __shared__ float qsh[8][64];
    __shared__ float psh[8][248];
    const float* qp = qkv + (size_t)t * 1536 + head * 64;
    qsh[warp][lane] = qp[lane] * 0.125f;
    qsh[warp][lane + 32] = qp[lane + 32] * 0.125f;
    __syncwarp();

    float sc[8];
    float m = -1e30f;
#pragma unroll
    for (int it = 0; it < 8; it++) {
        int nb = it * 32 + lane;
        float dot = -1e30f;
        if (nb < 245) {
            int pk = g_npack[nb];
            int nd = d + (pk >> 16) - 2;
            int nh = hh + ((pk >> 8) & 255) - 3;
            int nw = ww + (pk & 255) - 3;
            if ((unsigned)nd < 4u && (unsigned)nh < 32u && (unsigned)nw < 64u) {
                int nt = t + g_ndelta[nb];
                const float4* kp = reinterpret_cast<const float4*>(
                    qkv + (size_t)nt * 1536 + 512 + head * 64);
                float s = 0.f;
#pragma unroll
                for (int q4 = 0; q4 < 16; q4++) {
                    float4 kv = kp[q4];
                    s = fmaf(qsh[warp][q4 * 4 + 0], kv.x, s);
                    s = fmaf(qsh[warp][q4 * 4 + 1], kv.y, s);
                    s = fmaf(qsh[warp][q4 * 4 + 2], kv.z, s);
                    s = fmaf(qsh[warp][q4 * 4 + 3], kv.w, s);
                }
                dot = s;
            }
        }
        sc[it] = dot;
        m = fmaxf(m, dot);
    }
#pragma unroll
    for (int o = 16; o; o >>= 1) m = fmaxf(m, __shfl_xor_sync(0xffffffffu, m, o));

    float l = 0.f;
#pragma unroll
    for (int it = 0; it < 8; it++) {
        int nb = it * 32 + lane;
        float e = (sc[it] > -1e29f) ? __expf(sc[it] - m) : 0.f;
        if (nb < 248) psh[warp][nb] = e;
        l += e;
    }
#pragma unroll
    for (int o = 16; o; o >>= 1) l += __shfl_xor_sync(0xffffffffu, l, o);
    __syncwarp();

    float acc0 = 0.f, acc1 = 0.f;
    for (int nb = 0; nb < 245; nb++) {
        float pb = psh[warp][nb];
        if (pb > 0.f) {
            int nt = t + g_ndelta[nb];
            const float* vp = qkv + (size_t)nt * 1536 + 1024 + head * 64;
            acc0 = fmaf(pb, vp[lane], acc0);
            acc1 = fmaf(pb, vp[lane + 32], acc1);
        }
    }
    float inv = 1.f / l;
    float* op = at + (size_t)t * 512 + head * 64;
    op[lane] = acc0 * inv;
    op[lane + 32] = acc1 * inv;
}

// ---------------------------------------------------------------------------
// Host launcher
// ---------------------------------------------------------------------------
static inline int kpad64(int k) { return (k + 63) & ~63; }

extern "C" void kernel_launch(void* const* d_in, const int* in_sizes, int n_in,
                              void* d_out, int out_size) {
    const float* x2d  = (const float*)d_in[0];
    const float* x3d  = (const float*)d_in[1];
    const float* sw0  = (const float*)d_in[2];  const float* sb0 = (const float*)d_in[3];
    const float* sw1  = (const float*)d_in[4];  const float* sb1 = (const float*)d_in[5];
    const float* sw2  = (const float*)d_in[6];  const float* sb2 = (const float*)d_in[7];
    const float* pw0  = (const float*)d_in[8];  const float* pb0 = (const float*)d_in[9];
    const float* pw1  = (const float*)d_in[10]; const float* pb1 = (const float*)d_in[11];
    const float* pw2  = (const float*)d_in[12]; const float* pb2 = (const float*)d_in[13];
    const float* latw = (const float*)d_in[14]; const float* latb = (const float*)d_in[15];
    const float* lng  = (const float*)d_in[16]; const float* lnb  = (const float*)d_in[17];
    const float* qkvw = (const float*)d_in[18]; const float* qkvb = (const float*)d_in[19];
    const float* pjw  = (const float*)d_in[20]; const float* pjb  = (const float*)d_in[21];
    float* lat = (float*)d_out;

    float *s0, *s1, *p0, *p1, *feats, *yn, *qkvB, *at;
    cudaGetSymbolAddress((void**)&s0, g_s0);
    cudaGetSymbolAddress((void**)&s1, g_s1);
    cudaGetSymbolAddress((void**)&p0, g_p0);
    cudaGetSymbolAddress((void**)&p1, g_p1);
    cudaGetSymbolAddress((void**)&feats, g_feats);
    cudaGetSymbolAddress((void**)&yn, g_yn);
    cudaGetSymbolAddress((void**)&qkvB, g_qkv);
    cudaGetSymbolAddress((void**)&at, g_at);

    cudaFuncSetAttribute(conv_mma_kernel,
                         cudaFuncAttributeMaxDynamicSharedMemorySize, CONV_SMEM_BYTES);

    natt_table_kernel<<<1, 256>>>();

    // ---- 2D conv tower ----
    {
        int K = 72, Kp = kpad64(K);
        conv_decode_kernel<<<(Kp + 255) / 256, 256>>>(K, Kp, 9, 9, 3, 1, 256, 512);
        ConvParams p{ x2d, sw0, sb0, s0, 1, 256, 512, 128, 256,
                      1, 2, 2, 0, 1, 1, K, Kp, 32768, 0, 1 };
        conv_mma_kernel<<<dim3(32768 / 128, 1), 256, CONV_SMEM_BYTES>>>(p);
    }
    {
        int K = 1152, Kp = kpad64(K);
        conv_decode_kernel<<<(Kp + 255) / 256, 256>>>(K, Kp, 9, 9, 3, 1, 128, 256);
        ConvParams p{ s0, sw1, sb1, s1, 1, 128, 256, 64, 128,
                      1, 2, 2, 0, 1, 1, K, Kp, 8192, 0, 1 };
        conv_mma_kernel<<<dim3(8192 / 128, 2), 256, CONV_SMEM_BYTES>>>(p);
    }
    {
        int K = 2304, Kp = kpad64(K);
        conv_decode_kernel<<<(Kp + 255) / 256, 256>>>(K, Kp, 9, 9, 3, 1, 64, 128);
        ConvParams p{ s1, sw2, sb2, feats, 1, 64, 128, 32, 64,
                      1, 2, 2, 0, 1, 1, K, Kp, 8192, 3 * 2048, 1 };
        conv_mma_kernel<<<dim3(2048 / 128, 4), 256, CONV_SMEM_BYTES>>>(p);
    }

    // ---- 3D conv tower ----
    {
        int K = 135, Kp = kpad64(K);
        conv_decode_kernel<<<(Kp + 255) / 256, 256>>>(K, Kp, 27, 9, 3, 24, 256, 512);
        ConvParams p{ x3d, pw0, pb0, p0, 24, 256, 512, 128, 256,
                      2, 2, 2, 1, 1, 1, K, Kp, 393216, 0, 1 };
        conv_mma_kernel<<<dim3(393216 / 128, 1), 256, CONV_SMEM_BYTES>>>(p);
    }
    {
        int K = 3456, Kp = kpad64(K);
        conv_decode_kernel<<<(Kp + 255) / 256, 256>>>(K, Kp, 27, 9, 3, 12, 128, 256);
        ConvParams p{ p0, pw1, pb1, p1, 12, 128, 256, 64, 128,
                      2, 2, 2, 1, 1, 1, K, Kp, 49152, 0, 1 };
        conv_mma_kernel<<<dim3(49152 / 128, 2), 256, CONV_SMEM_BYTES>>>(p);
    }
    {
        int K = 6912, Kp = kpad64(K);
        conv_decode_kernel<<<(Kp + 255) / 256, 256>>>(K, Kp, 27, 9, 3, 6, 64, 128);
        ConvParams p{ p1, pw2, pb2, feats, 6, 64, 128, 32, 64,
                      2, 2, 2, 1, 1, 1, K, Kp, 8192, 0, 1 };
        conv_mma_kernel<<<dim3(6144 / 128, 4), 256, CONV_SMEM_BYTES>>>(p);
    }

    // ---- lateral 1x1x1 conv -> d_out ----
    {
        int K = 512, Kp = 512;
        conv_decode_kernel<<<(Kp + 255) / 256, 256>>>(K, Kp, 1, 1, 1, 4, 32, 64);
        ConvParams p{ feats, latw, latb, lat, 4, 32, 64, 32, 64,
                      1, 1, 1, 0, 0, 0, K, Kp, 8192, 0, 0 };
        conv_mma_kernel<<<dim3(8192 / 128, 4), 256, CONV_SMEM_BYTES>>>(p);
    }

    // ---- 3 neighborhood-attention blocks ----
    for (int i = 0; i < 3; i++) {
        layernorm_kernel<<<8192 / 32, dim3(32, 8)>>>(lat, lng + i * 512, lnb + i * 512,
                                                     yn, 8192);
        tok_gemm_kernel<0, 0><<<dim3(1536 / 128, 8192 / 64), 256>>>(
            yn, qkvw + (size_t)i * 512 * 1536, qkvb + i * 1536, qkvB, 8192, 1536, 512);
        natt_kernel<<<dim3(8192 / 8, 8), 256>>>(qkvB, at);
        tok_gemm_kernel<1, 1><<<dim3(512 / 128, 8192 / 64), 256>>>(
            at, pjw + (size_t)i * 512 * 512, pjb + i * 512, lat, 8192, 512, 512);
    }
}

// round 5
// speedup vs baseline: 1.2891x; 1.2891x over previous
#include <cuda_runtime.h>
#include <cuda_bf16.h>
#include <math.h>
#include <cstdint>

#if defined(__CUDA_ARCH_SPECIFIC__) || defined(__CUDA_ARCH_FEAT_SM103_ALL)
#define HAS_TCGEN05 1
#else
#define HAS_TCGEN05 0
#endif

// ---------------------------------------------------------------------------
// Scratch buffers (packed u32 = bf16 hi << 16 | bf16 lo)
// ---------------------------------------------------------------------------
__device__ uint32_t g_pk_a[15728640];   // ping: x2d/s1/x3d/p1
__device__ uint32_t g_pk_b[50331648];   // pong: s0/p0
__device__ uint32_t g_pk_f[4194304];    // feats packed [512][8192]
__device__ uint8_t  g_wpk[14155776];    // prepacked swizzled weight tiles
__device__ float    g_yn[512 * 8192];
__device__ float    g_qkv[8192 * 1536];
__device__ float    g_at[8192 * 512];
__device__ int2     g_dec[8192];
__device__ int      g_ndelta[256];
__device__ int      g_npack[256];

// ---------------------------------------------------------------------------
// Common helpers
// ---------------------------------------------------------------------------
__device__ __forceinline__ uint32_t smem_u32(const void* p) {
    uint32_t a;
    asm("{ .reg .u64 t; cvta.to.shared.u64 t, %1; cvt.u32.u64 %0, t; }"
        : "=r"(a) : "l"(p));
    return a;
}
__device__ __forceinline__ float gelu_tanh(float x) {
    float x3 = x * x * x;
    float t = tanhf(0.7978845608028654f * (x + 0.044715f * x3));
    return 0.5f * x * (1.0f + t);
}
__device__ __forceinline__ uint32_t pack_hl(float f) {
    __nv_bfloat16 h = __float2bfloat16(f);
    __nv_bfloat16 l = __float2bfloat16(f - __bfloat162float(h));
    return ((uint32_t)__bfloat16_as_ushort(h) << 16) | __bfloat16_as_ushort(l);
}
__device__ __forceinline__ float unpack_hl(uint32_t v) {
    float h = __bfloat162float(__ushort_as_bfloat16((unsigned short)(v >> 16)));
    float l = __bfloat162float(__ushort_as_bfloat16((unsigned short)(v & 0xFFFF)));
    return h + l;
}

#if HAS_TCGEN05
__device__ __forceinline__ uint32_t elect_one() {
    uint32_t pred;
    asm volatile("{ .reg .pred p; elect.sync _|p, 0xFFFFFFFF; selp.b32 %0, 1, 0, p; }"
                 : "=r"(pred));
    return pred;
}
#define TCGEN05_ALLOC(a, n) \
    asm volatile("tcgen05.alloc.cta_group::1.sync.aligned.shared::cta.b32 [%0], %1;" \
                 :: "r"((uint32_t)(a)), "r"((uint32_t)(n)) : "memory")
#define TCGEN05_DEALLOC(t, n) \
    asm volatile("tcgen05.dealloc.cta_group::1.sync.aligned.b32 %0, %1;" :: "r"(t), "r"(n))
#define TCGEN05_RELINQ() \
    asm volatile("tcgen05.relinquish_alloc_permit.cta_group::1.sync.aligned;")
#define TCGEN05_COMMIT(m) \
    asm volatile("tcgen05.commit.cta_group::1.mbarrier::arrive::one.shared::cluster.b64 [%0];" \
                 :: "r"((uint32_t)(m)) : "memory")
#define TCGEN05_FENCE_AFTER() \
    asm volatile("tcgen05.fence::after_thread_sync;" ::: "memory")
#define TCGEN05_FENCE_BEFORE() \
    asm volatile("tcgen05.fence::before_thread_sync;" ::: "memory")
#define TCGEN05_WAIT_LD() asm volatile("tcgen05.wait::ld.sync.aligned;" ::: "memory")
#define FENCE_PROXY_ASYNC() asm volatile("fence.proxy.async.shared::cta;" ::: "memory")
#define MBARRIER_INIT(m, c) \
    asm volatile("mbarrier.init.shared.b64 [%0], %1;" :: "r"((uint32_t)(m)), "r"((uint32_t)(c)) : "memory")
#define MBARRIER_INVAL(m) \
    asm volatile("mbarrier.inval.shared.b64 [%0];" :: "r"((uint32_t)(m)) : "memory")
#define MBARRIER_WAIT_PARITY(m, ph) do {                                           \
    uint32_t _m = (uint32_t)(m), _p = (uint32_t)(ph), _d;                          \
    asm volatile("{ .reg .pred p; mbarrier.try_wait.parity.acquire.cta.shared::cta.b64 p, [%1], %2;" \
                 " selp.b32 %0, 1, 0, p; }" : "=r"(_d) : "r"(_m), "r"(_p) : "memory"); \
    if (!_d) {                                                                     \
        asm volatile("{ .reg .pred P1; WL_%=: mbarrier.try_wait.parity.acquire.cta.shared::cta.b64 P1, [%0], %1, 0x989680;" \
                     " @P1 bra.uni WD_%=; bra.uni WL_%=; WD_%=: }"                 \
                     :: "r"(_m), "r"(_p) : "memory");                              \
    }                                                                              \
} while (0)
#define TCGEN05_LD_X32(r, a)                                                       \
    asm volatile("tcgen05.ld.sync.aligned.32x32b.x32.b32 "                         \
        "{%0, %1, %2, %3, %4, %5, %6, %7, %8, %9, %10, %11, %12, %13, %14, %15, "  \
        " %16, %17, %18, %19, %20, %21, %22, %23, %24, %25, %26, %27, %28, %29, %30, %31}, [%32];" \
        : "=r"((r)[0]), "=r"((r)[1]), "=r"((r)[2]), "=r"((r)[3]),                  \
          "=r"((r)[4]), "=r"((r)[5]), "=r"((r)[6]), "=r"((r)[7]),                  \
          "=r"((r)[8]), "=r"((r)[9]), "=r"((r)[10]), "=r"((r)[11]),                \
          "=r"((r)[12]), "=r"((r)[13]), "=r"((r)[14]), "=r"((r)[15]),              \
          "=r"((r)[16]), "=r"((r)[17]), "=r"((r)[18]), "=r"((r)[19]),              \
          "=r"((r)[20]), "=r"((r)[21]), "=r"((r)[22]), "=r"((r)[23]),              \
          "=r"((r)[24]), "=r"((r)[25]), "=r"((r)[26]), "=r"((r)[27]),              \
          "=r"((r)[28]), "=r"((r)[29]), "=r"((r)[30]), "=r"((r)[31])               \
        : "r"(a))

static constexpr uint64_t SMEM_DESC_BASE_SW128 =
    (uint64_t(2) << 61) | (uint64_t(1) << 46) | (uint64_t(64) << 32) | (uint64_t(1) << 16);
__device__ __forceinline__ uint64_t make_desc(uint32_t addr) {
    return SMEM_DESC_BASE_SW128 | ((uint64_t)(addr >> 4) & 0x3FFF);
}
__device__ __forceinline__ void mma_f16_ss(uint32_t d, uint64_t ad, uint64_t bd,
                                           uint32_t idesc, uint32_t en) {
    asm volatile(
        "{ .reg .pred p; setp.ne.u32 p, %5, 0;\n\t"
        "tcgen05.mma.cta_group::1.kind::f16 [%0], %1, %2, %3, {%4, %4, %4, %4}, p; }"
        :: "r"(d), "l"(ad), "l"(bd), "r"(idesc), "r"(0u), "r"(en) : "memory");
}
// idesc: F32 out, BF16 x BF16, N=128, M=128
static constexpr uint32_t CONV_IDESC =
    (1u << 4) | (1u << 7) | (1u << 10) | ((128u / 8) << 17) | ((128u / 16) << 24);
#endif // HAS_TCGEN05

// ---------------------------------------------------------------------------
// Init / pack kernels
// ---------------------------------------------------------------------------
__global__ void conv_decode_kernel(int K, int Kpad, int KV, int KHW, int KW,
                                   int D, int H, int W) {
    int k = blockIdx.x * 256 + threadIdx.x;
    if (k >= Kpad) return;
    if (k < K) {
        int ci = k / KV; int tap = k - ci * KV;
        int kd = tap / KHW; int t2 = tap - kd * KHW;
        int kh = t2 / KW; int kw = t2 - kh * KW;
        g_dec[k] = make_int2(((ci * D + kd) * H + kh) * W + kw,
                             (kd << 20) | (kh << 10) | kw);
    } else {
        g_dec[k] = make_int2(0, 1023 << 20);
    }
}

__global__ void natt_table_kernel() {
    int nb = threadIdx.x;
    if (nb < 245) {
        int od = nb / 49; int r = nb - od * 49;
        int oh = r / 7;   int ow = r - oh * 7;
        g_ndelta[nb] = (od - 2) * 2048 + (oh - 3) * 64 + (ow - 3);
        g_npack[nb]  = (od << 16) | (oh << 8) | ow;
    }
}

// pack fp32 tensor -> u32 (hi,lo) packed, 4 per thread
__global__ void xpack_kernel(const float* __restrict__ x,
                             uint32_t* __restrict__ dst, int n4) {
    int i = blockIdx.x * 256 + threadIdx.x;
    if (i >= n4) return;
    float4 v = reinterpret_cast<const float4*>(x)[i];
    uint4 o;
    o.x = pack_hl(v.x); o.y = pack_hl(v.y);
    o.z = pack_hl(v.z); o.w = pack_hl(v.w);
    reinterpret_cast<uint4*>(dst)[i] = o;
}

// prepack conv weights into swizzled smem-image tiles: [bm*NC+kc][hi 16K][lo 16K]
__global__ void wpack_kernel(const float* __restrict__ w, int K, int NC) {
    int kc = blockIdx.x, bm = blockIdx.y;
    int tid = threadIdx.x;
    int r = tid >> 1, half = tid & 1;
    const float* wrow = w + (size_t)(bm * 128 + r) * K;
    uint8_t* hi = g_wpk + (size_t)(bm * NC + kc) * 32768;
    uint8_t* lo = hi + 16384;
#pragma unroll
    for (int i = 0; i < 16; i++) {
        int kk = half * 32 + 2 * i;
        int k = kc * 64 + kk;
        float a0 = (k < K) ? wrow[k] : 0.f;
        float a1 = (k + 1 < K) ? wrow[k + 1] : 0.f;
        uint32_t p0 = pack_hl(a0), p1 = pack_hl(a1);
        uint32_t hp = __byte_perm(p0, p1, 0x7632);   // (h1<<16)|h0
        uint32_t lp = __byte_perm(p0, p1, 0x5410);   // (l1<<16)|l0
        uint32_t off = r * 128 + kk * 2;
        uint32_t sw = off ^ ((off >> 3) & 0x70);
        *reinterpret_cast<uint32_t*>(hi + sw) = hp;
        *reinterpret_cast<uint32_t*>(lo + sw) = lp;
    }
}

// ---------------------------------------------------------------------------
// Conv kernel: tcgen05 MMA, packed-u32 input gather, prepacked weights.
// Tile M=128 x N=128, K chunks of 64. Block 512 threads. Grid (N/128, Cout/128).
// ---------------------------------------------------------------------------
struct ConvParams {
    const uint32_t* xpk;      // packed input
    const float* wf;          // fp32 weights (fallback only)
    const float* bias;
    uint32_t* outpk;          // packed output (or null)
    float* outf;              // fp32 output (or null)
    int D, H, W;
    int Hout, Wout;
    int sd, sh, sw, pd, ph, pw;
    int K, NC;                // NC = Kpad/64
    int outStrideC, outOffset;
    int gelu;
};

#define CONV_SMEM_BYTES (1024 + 8 * 16384 + 64)

__global__ __launch_bounds__(512) void conv_mma_kernel(ConvParams p) {
    extern __shared__ char smem_raw[];
    char* smem_al = (char*)(((uintptr_t)smem_raw + 1023) & ~(uintptr_t)1023);

    const int tid = threadIdx.x;
    const int bn = blockIdx.x, bm = blockIdx.y;
    const int m_base = bm * 128;
    const int HWo = p.Hout * p.Wout;

#if HAS_TCGEN05
    const uint32_t sb = smem_u32(smem_al);
    const uint32_t mbar = sb + 131072;
    const uint32_t tmem_slot = sb + 131080;
    const int wid = tid >> 5;
    const int lane = tid & 31;

    if (wid == 0) {
        TCGEN05_ALLOC(tmem_slot, 128);
        TCGEN05_RELINQ();
    }
    if (tid == 0) MBARRIER_INIT(mbar, 1);
    __syncthreads();
    uint32_t tmem;
    asm volatile("ld.shared.b32 %0, [%1];" : "=r"(tmem) : "r"(tmem_slot));

    // B-fill geometry: row r (0..127 = output voxel), k-quarter q (16 k each)
    const int r = tid >> 2;
    const int q = tid & 3;
    const int n = bn * 128 + r;
    const int od = n / HWo; int rr2 = n - od * HWo;
    const int oh = rr2 / p.Wout; const int ow = rr2 - oh * p.Wout;
    const int id0 = od * p.sd - p.pd;
    const int ih0 = oh * p.sh - p.ph;
    const int iw0 = ow * p.sw - p.pw;
    const int gbase = (id0 * p.H + ih0) * p.W + iw0;
    const uint8_t* wsrc_base = g_wpk + (size_t)bm * p.NC * 32768;

    const int NC = p.NC;

    auto fill = [&](int st, int kc) {
        char* stage = smem_al + st * 65536;
        // A: straight 32KB copy of prepacked tiles (hi+lo)
        {
            const uint8_t* src = wsrc_base + (size_t)kc * 32768 + tid * 16;
            char* dst = stage + tid * 16;
#pragma unroll
            for (int i = 0; i < 4; i++) {
                uint4 v = *reinterpret_cast<const uint4*>(src + i * 8192);
                *reinterpret_cast<uint4*>(dst + i * 8192) = v;
            }
        }
        // B: gather 16 k-elements (8 pairs) for row r
        char* Bhi = stage + 32768;
        char* Blo = stage + 49152;
        const int kt = kc * 64;
#pragma unroll
        for (int i = 0; i < 8; i++) {
            int kk = q * 16 + 2 * i;
            int k = kt + kk;
            int4 dv = *reinterpret_cast<const int4*>(&g_dec[k]);
            uint32_t v0 = 0, v1 = 0;
            {
                int kd = dv.y >> 20, kh = (dv.y >> 10) & 1023, kw = dv.y & 1023;
                if ((unsigned)(id0 + kd) < (unsigned)p.D &&
                    (unsigned)(ih0 + kh) < (unsigned)p.H &&
                    (unsigned)(iw0 + kw) < (unsigned)p.W)
                    v0 = p.xpk[gbase + dv.x];
            }
            {
                int kd = dv.w >> 20, kh = (dv.w >> 10) & 1023, kw = dv.w & 1023;
                if ((unsigned)(id0 + kd) < (unsigned)p.D &&
                    (unsigned)(ih0 + kh) < (unsigned)p.H &&
                    (unsigned)(iw0 + kw) < (unsigned)p.W)
                    v1 = p.xpk[gbase + dv.z];
            }
            uint32_t off = r * 128 + kk * 2;
            uint32_t sw = off ^ ((off >> 3) & 0x70);
            *reinterpret_cast<uint32_t*>(Bhi + sw) = __byte_perm(v0, v1, 0x7632);
            *reinterpret_cast<uint32_t*>(Blo + sw) = __byte_perm(v0, v1, 0x5410);
        }
    };

    fill(0, 0);
    FENCE_PROXY_ASYNC();
    __syncthreads();

    int wpar = 0;
    uint32_t first = 0;

    for (int kc = 0; kc < NC; kc++) {
        int st = kc & 1;
        if (wid == 0 && elect_one()) {
            uint32_t stb = sb + st * 65536;
            uint64_t dAh = make_desc(stb);
            uint64_t dAl = make_desc(stb + 16384);
            uint64_t dBh = make_desc(stb + 32768);
            uint64_t dBl = make_desc(stb + 49152);
#pragma unroll
            for (int s = 0; s < 4; s++) {
                uint64_t o = s * 2;
                mma_f16_ss(tmem, dAh + o, dBh + o, CONV_IDESC, first); first = 1;
                mma_f16_ss(tmem, dAh + o, dBl + o, CONV_IDESC, 1);
                mma_f16_ss(tmem, dAl + o, dBh + o, CONV_IDESC, 1);
            }
            TCGEN05_COMMIT(mbar);
        }
        if (kc + 1 < NC) {
            if (kc >= 1) { MBARRIER_WAIT_PARITY(mbar, wpar & 1); wpar++; }
            fill((kc + 1) & 1, kc + 1);
            FENCE_PROXY_ASYNC();
            __syncthreads();
        }
    }
    while (wpar < NC) { MBARRIER_WAIT_PARITY(mbar, wpar & 1); wpar++; }
    TCGEN05_FENCE_AFTER();

    // epilogue: 16 warps, warp w -> subpartition w&3, column block w>>2
    {
        const int sp = wid & 3;
        const int cb = wid >> 2;
        const int m = m_base + sp * 32 + lane;
        const float bv = p.bias[m];
        uint32_t dr[32];
        TCGEN05_LD_X32(dr, tmem + cb * 32);
        TCGEN05_WAIT_LD();
        size_t obase = (size_t)m * p.outStrideC + p.outOffset + bn * 128 + cb * 32;
        if (p.outpk) {
            uint32_t* orow = p.outpk + obase;
#pragma unroll
            for (int j = 0; j < 32; j++) {
                float v = __uint_as_float(dr[j]) + bv;
                if (p.gelu) v = gelu_tanh(v);
                orow[j] = pack_hl(v);
            }
        } else {
            float* orow = p.outf + obase;
#pragma unroll
            for (int j = 0; j < 32; j++) {
                float v = __uint_as_float(dr[j]) + bv;
                if (p.gelu) v = gelu_tanh(v);
                orow[j] = v;
            }
        }
        TCGEN05_FENCE_BEFORE();
    }
    __syncthreads();
    if (tid == 0) MBARRIER_INVAL(mbar);
    if (wid == 0) TCGEN05_DEALLOC(tmem, 128);

#else  // ----------------- FFMA fallback (never executes on GB300) -----------
    const int tx = tid & 15, ty = tid >> 4;   // n-group of 8, m-group of 4
    const int n0 = bn * 128 + tx * 8;
    float acc[4][8];
#pragma unroll
    for (int i = 0; i < 4; i++)
#pragma unroll
        for (int j = 0; j < 8; j++) acc[i][j] = 0.f;

    int id0s[8], ih0s[8], iw0s[8], gb[8];
    for (int j = 0; j < 8; j++) {
        int n = n0 + j;
        int od = n / HWo; int rr2 = n - od * HWo;
        int oh = rr2 / p.Wout; int ow = rr2 - oh * p.Wout;
        id0s[j] = od * p.sd - p.pd;
        ih0s[j] = oh * p.sh - p.ph;
        iw0s[j] = ow * p.sw - p.pw;
        gb[j] = (id0s[j] * p.H + ih0s[j]) * p.W + iw0s[j];
    }
    for (int k = 0; k < p.K; k++) {
        int2 dv = g_dec[k];
        int kd = dv.y >> 20, kh = (dv.y >> 10) & 1023, kw = dv.y & 1023;
        float b[8];
        for (int j = 0; j < 8; j++) {
            b[j] = 0.f;
            if ((unsigned)(id0s[j] + kd) < (unsigned)p.D &&
                (unsigned)(ih0s[j] + kh) < (unsigned)p.H &&
                (unsigned)(iw0s[j] + kw) < (unsigned)p.W)
                b[j] = unpack_hl(p.xpk[gb[j] + dv.x]);
        }
        for (int i = 0; i < 4; i++) {
            float a = p.wf[(size_t)(m_base + ty * 4 + i) * p.K + k];
            for (int j = 0; j < 8; j++) acc[i][j] = fmaf(a, b[j], acc[i][j]);
        }
    }
    for (int i = 0; i < 4; i++) {
        int m = m_base + ty * 4 + i;
        float bvl = p.bias[m];
        size_t obase = (size_t)m * p.outStrideC + p.outOffset + n0;
        for (int j = 0; j < 8; j++) {
            float v = acc[i][j] + bvl;
            if (p.gelu) v = gelu_tanh(v);
            if (p.outpk) p.outpk[obase + j] = pack_hl(v);
            else p.outf[obase + j] = v;
        }
    }
#endif
}

// ---------------------------------------------------------------------------
// Token GEMM (fp32, unchanged)
// ---------------------------------------------------------------------------
template <int ALAYOUT, int OUTMODE>
__global__ __launch_bounds__(256) void tok_gemm_kernel(
    const float* __restrict__ A, const float* __restrict__ B,
    const float* __restrict__ bias, float* __restrict__ C,
    int T, int J, int K) {
    __shared__ __align__(16) float As[16][64];
    __shared__ __align__(16) float Bs[16][128];

    const int tid = threadIdx.x;
    const int bj = blockIdx.x, bt = blockIdx.y;
    const int tx = tid & 15, ty = tid >> 4;
    const int lj = tid & 127, kgrp2 = tid >> 7;

    float acc[4][8];
#pragma unroll
    for (int i = 0; i < 4; i++)
#pragma unroll
        for (int j = 0; j < 8; j++) acc[i][j] = 0.f;

    for (int kt = 0; kt < K; kt += 16) {
        if (ALAYOUT == 0) {
            const int lt = tid & 63, kg = tid >> 6;
#pragma unroll
            for (int r = 0; r < 4; r++) {
                int kk = kg * 4 + r;
                As[kk][lt] = A[(size_t)(kt + kk) * T + bt * 64 + lt];
            }
        } else {
            const int lt = tid >> 2, lk4 = (tid & 3) << 2;
            float4 v = *reinterpret_cast<const float4*>(
                A + (size_t)(bt * 64 + lt) * K + kt + lk4);
            As[lk4 + 0][lt] = v.x; As[lk4 + 1][lt] = v.y;
            As[lk4 + 2][lt] = v.z; As[lk4 + 3][lt] = v.w;
        }
#pragma unroll
        for (int r = 0; r < 8; r++) {
            int kk = kgrp2 * 8 + r;
            Bs[kk][lj] = B[(size_t)(kt + kk) * J + bj * 128 + lj];
        }
        __syncthreads();
#pragma unroll
        for (int kq = 0; kq < 16; kq++) {
            float4 a  = *reinterpret_cast<const float4*>(&As[kq][ty * 4]);
            float4 b0 = *reinterpret_cast<const float4*>(&Bs[kq][tx * 4]);
            float4 b1 = *reinterpret_cast<const float4*>(&Bs[kq][64 + tx * 4]);
            float av[4] = {a.x, a.y, a.z, a.w};
            float bv[8] = {b0.x, b0.y, b0.z, b0.w, b1.x, b1.y, b1.z, b1.w};
#pragma unroll
            for (int i = 0; i < 4; i++)
#pragma unroll
                for (int j = 0; j < 8; j++)
                    acc[i][j] = fmaf(av[i], bv[j], acc[i][j]);
        }
        __syncthreads();
    }

    if (OUTMODE == 0) {
#pragma unroll
        for (int i = 0; i < 4; i++) {
            int t = bt * 64 + ty * 4 + i;
            int j0 = bj * 128 + tx * 4;
            int j1 = j0 + 64;
            float4 o0, o1;
            o0.x = acc[i][0] + bias[j0 + 0]; o0.y = acc[i][1] + bias[j0 + 1];
            o0.z = acc[i][2] + bias[j0 + 2]; o0.w = acc[i][3] + bias[j0 + 3];
            o1.x = acc[i][4] + bias[j1 + 0]; o1.y = acc[i][5] + bias[j1 + 1];
            o1.z = acc[i][6] + bias[j1 + 2]; o1.w = acc[i][7] + bias[j1 + 3];
            *reinterpret_cast<float4*>(C + (size_t)t * J + j0) = o0;
            *reinterpret_cast<float4*>(C + (size_t)t * J + j1) = o1;
        }
    } else {
        int t0 = bt * 64 + ty * 4;
#pragma unroll
        for (int j = 0; j < 4; j++) {
            int jj = bj * 128 + tx * 4 + j;
            float bvl = bias[jj];
            float4* cp = reinterpret_cast<float4*>(C + (size_t)jj * T + t0);
            float4 o = *cp;
            o.x += acc[0][j] + bvl; o.y += acc[1][j] + bvl;
            o.z += acc[2][j] + bvl; o.w += acc[3][j] + bvl;
            *cp = o;
        }
#pragma unroll
        for (int j = 0; j < 4; j++) {
            int jj = bj * 128 + 64 + tx * 4 + j;
            float bvl = bias[jj];
            float4* cp = reinterpret_cast<float4*>(C + (size_t)jj * T + t0);
            float4 o = *cp;
            o.x += acc[0][4 + j] + bvl; o.y += acc[1][4 + j] + bvl;
            o.z += acc[2][4 + j] + bvl; o.w += acc[3][4 + j] + bvl;
            *cp = o;
        }
    }
}

// ---------------------------------------------------------------------------
// LayerNorm (unchanged)
// ---------------------------------------------------------------------------
__global__ __launch_bounds__(256) void layernorm_kernel(
    const float* __restrict__ x, const float* __restrict__ g,
    const float* __restrict__ b, float* __restrict__ y, int T) {
    const int tx = threadIdx.x;
    const int ty = threadIdx.y;
    const int t = blockIdx.x * 32 + tx;

    float s = 0.f, ss = 0.f;
#pragma unroll
    for (int i = 0; i < 64; i++) {
        int c = ty * 64 + i;
        float v = x[(size_t)c * T + t];
        s += v; ss += v * v;
    }
    __shared__ float shs[8][32], shss[8][32];
    __shared__ float smu[32], srs[32];
    shs[ty][tx] = s; shss[ty][tx] = ss;
    __syncthreads();
    if (ty == 0) {
        float S = 0.f, SS = 0.f;
#pragma unroll
        for (int j = 0; j < 8; j++) { S += shs[j][tx]; SS += shss[j][tx]; }
        float mu = S * (1.f / 512.f);
        float var = SS * (1.f / 512.f) - mu * mu;
        smu[tx] = mu;
        srs[tx] = rsqrtf(var + 1e-5f);
    }
    __syncthreads();
    float mu = smu[tx], rs = srs[tx];
#pragma unroll
    for (int i = 0; i < 64; i++) {
        int c = ty * 64 + i;
        float v = x[(size_t)c * T + t];
        y[(size_t)c * T + t] = (v - mu) * rs * g[c] + b[c];
    }
}

// ---------------------------------------------------------------------------
// Neighborhood attention (unchanged)
// ---------------------------------------------------------------------------
__global__ __launch_bounds__(256) void natt_kernel(
    const float* __restrict__ qkv, float* __restrict__ at) {
    const int warp = threadIdx.x >> 5;
    const int lane = threadIdx.x & 31;
    const int t = blockIdx.x * 8 + warp;
    const int head = blockIdx.y;
    const int d = t >> 11;
    const int hh = (t >> 6) & 31;
    const int ww = t & 63;

    __shared__ float qsh[8][64];
    __shared__ float psh[8][248];
    const float* qp = qkv + (size_t)t * 1536 + head * 64;
    qsh[warp][lane] = qp[lane] * 0.125f;
    qsh[warp][lane + 32] = qp[lane + 32] * 0.125f;
    __syncwarp();

    float sc[8];
    float m = -1e30f;
#pragma unroll
    for (int it = 0; it < 8; it++) {
        int nb = it * 32 + lane;
        float dot = -1e30f;
        if (nb < 245) {
            int pk = g_npack[nb];
            int nd = d + (pk >> 16) - 2;
            int nh = hh + ((pk >> 8) & 255) - 3;
            int nw = ww + (pk & 255) - 3;
            if ((unsigned)nd < 4u && (unsigned)nh < 32u && (unsigned)nw < 64u) {
                int nt = t + g_ndelta[nb];
                const float4* kp = reinterpret_cast<const float4*>(
                    qkv + (size_t)nt * 1536 + 512 + head * 64);
                float s = 0.f;
#pragma unroll
                for (int q4 = 0; q4 < 16; q4++) {
                    float4 kv = kp[q4];
                    s = fmaf(qsh[warp][q4 * 4 + 0], kv.x, s);
                    s = fmaf(qsh[warp][q4 * 4 + 1], kv.y, s);
                    s = fmaf(qsh[warp][q4 * 4 + 2], kv.z, s);
                    s = fmaf(qsh[warp][q4 * 4 + 3], kv.w, s);
                }
                dot = s;
            }
        }
        sc[it] = dot;
        m = fmaxf(m, dot);
    }
#pragma unroll
    for (int o = 16; o; o >>= 1) m = fmaxf(m, __shfl_xor_sync(0xffffffffu, m, o));

    float l = 0.f;
#pragma unroll
    for (int it = 0; it < 8; it++) {
        int nb = it * 32 + lane;
        float e = (sc[it] > -1e29f) ? __expf(sc[it] - m) : 0.f;
        if (nb < 248) psh[warp][nb] = e;
        l += e;
    }
#pragma unroll
    for (int o = 16; o; o >>= 1) l += __shfl_xor_sync(0xffffffffu, l, o);
    __syncwarp();

    float acc0 = 0.f, acc1 = 0.f;
    for (int nb = 0; nb < 245; nb++) {
        float pb = psh[warp][nb];
        if (pb > 0.f) {
            int nt = t + g_ndelta[nb];
            const float* vp = qkv + (size_t)nt * 1536 + 1024 + head * 64;
            acc0 = fmaf(pb, vp[lane], acc0);
            acc1 = fmaf(pb, vp[lane + 32], acc1);
        }
    }
    float inv = 1.f / l;
    float* op = at + (size_t)t * 512 + head * 64;
    op[lane] = acc0 * inv;
    op[lane + 32] = acc1 * inv;
}

// ---------------------------------------------------------------------------
// Host launcher
// ---------------------------------------------------------------------------
extern "C" void kernel_launch(void* const* d_in, const int* in_sizes, int n_in,
                              void* d_out, int out_size) {
    const float* x2d  = (const float*)d_in[0];
    const float* x3d  = (const float*)d_in[1];
    const float* sw0  = (const float*)d_in[2];  const float* sb0 = (const float*)d_in[3];
    const float* sw1  = (const float*)d_in[4];  const float* sb1 = (const float*)d_in[5];
    const float* sw2  = (const float*)d_in[6];  const float* sb2 = (const float*)d_in[7];
    const float* pw0  = (const float*)d_in[8];  const float* pb0 = (const float*)d_in[9];
    const float* pw1  = (const float*)d_in[10]; const float* pb1 = (const float*)d_in[11];
    const float* pw2  = (const float*)d_in[12]; const float* pb2 = (const float*)d_in[13];
    const float* latw = (const float*)d_in[14]; const float* latb = (const float*)d_in[15];
    const float* lng  = (const float*)d_in[16]; const float* lnb  = (const float*)d_in[17];
    const float* qkvw = (const float*)d_in[18]; const float* qkvb = (const float*)d_in[19];
    const float* pjw  = (const float*)d_in[20]; const float* pjb  = (const float*)d_in[21];
    float* lat = (float*)d_out;

    uint32_t *pkA, *pkB, *pkF;
    float *yn, *qkvB, *at;
    cudaGetSymbolAddress((void**)&pkA, g_pk_a);
    cudaGetSymbolAddress((void**)&pkB, g_pk_b);
    cudaGetSymbolAddress((void**)&pkF, g_pk_f);
    cudaGetSymbolAddress((void**)&yn, g_yn);
    cudaGetSymbolAddress((void**)&qkvB, g_qkv);
    cudaGetSymbolAddress((void**)&at, g_at);

    cudaFuncSetAttribute(conv_mma_kernel,
                         cudaFuncAttributeMaxDynamicSharedMemorySize, CONV_SMEM_BYTES);

    natt_table_kernel<<<1, 256>>>();

    auto run_conv = [&](const uint32_t* xpk, const float* wf, const float* bias,
                        uint32_t* outpk, float* outf,
                        int Cin, int D, int H, int W, int Dout, int Hout, int Wout,
                        int KD, int KH, int KW, int sd, int sh, int sw,
                        int pd, int ph, int pw, int Cout,
                        int outStrideC, int outOffset, int gelu) {
        int K = Cin * KD * KH * KW;
        int NC = (K + 63) / 64;
        int Kp = NC * 64;
        conv_decode_kernel<<<(Kp + 255) / 256, 256>>>(K, Kp, KD * KH * KW, KH * KW,
                                                      KW, D, H, W);
        wpack_kernel<<<dim3(NC, Cout / 128), 256>>>(wf, K, NC);
        int Nvox = Dout * Hout * Wout;
        ConvParams p{ xpk, wf, bias, outpk, outf,
                      D, H, W, Hout, Wout, sd, sh, sw, pd, ph, pw,
                      K, NC, outStrideC, outOffset, gelu };
        conv_mma_kernel<<<dim3(Nvox / 128, Cout / 128), 512, CONV_SMEM_BYTES>>>(p);
    };

    // ---- 2D tower ----
    xpack_kernel<<<(8 * 256 * 512 / 4 + 255) / 256, 256>>>(x2d, pkA, 8 * 256 * 512 / 4);
    run_conv(pkA, sw0, sb0, pkB, nullptr, 8, 1, 256, 512, 1, 128, 256,
             1, 3, 3, 1, 2, 2, 0, 1, 1, 128, 32768, 0, 1);
    run_conv(pkB, sw1, sb1, pkA, nullptr, 128, 1, 128, 256, 1, 64, 128,
             1, 3, 3, 1, 2, 2, 0, 1, 1, 256, 8192, 0, 1);
    run_conv(pkA, sw2, sb2, pkF, nullptr, 256, 1, 64, 128, 1, 32, 64,
             1, 3, 3, 1, 2, 2, 0, 1, 1, 512, 8192, 3 * 2048, 1);

    // ---- 3D tower ----
    xpack_kernel<<<(5 * 24 * 256 * 512 / 4 + 255) / 256, 256>>>(
        x3d, pkA, 5 * 24 * 256 * 512 / 4);
    run_conv(pkA, pw0, pb0, pkB, nullptr, 5, 24, 256, 512, 12, 128, 256,
             3, 3, 3, 2, 2, 2, 1, 1, 1, 128, 393216, 0, 1);
    run_conv(pkB, pw1, pb1, pkA, nullptr, 128, 12, 128, 256, 6, 64, 128,
             3, 3, 3, 2, 2, 2, 1, 1, 1, 256, 49152, 0, 1);
    run_conv(pkA, pw2, pb2, pkF, nullptr, 256, 6, 64, 128, 3, 32, 64,
             3, 3, 3, 2, 2, 2, 1, 1, 1, 512, 8192, 0, 1);

    // ---- lateral 1x1x1 -> d_out fp32 ----
    run_conv(pkF, latw, latb, nullptr, lat, 512, 4, 32, 64, 4, 32, 64,
             1, 1, 1, 1, 1, 1, 0, 0, 0, 512, 8192, 0, 0);

    // ---- 3 neighborhood-attention blocks ----
    for (int i = 0; i < 3; i++) {
        layernorm_kernel<<<8192 / 32, dim3(32, 8)>>>(lat, lng + i * 512, lnb + i * 512,
                                                     yn, 8192);
        tok_gemm_kernel<0, 0><<<dim3(1536 / 128, 8192 / 64), 256>>>(
            yn, qkvw + (size_t)i * 512 * 1536, qkvb + i * 1536, qkvB, 8192, 1536, 512);
        natt_kernel<<<dim3(8192 / 8, 8), 256>>>(qkvB, at);
        tok_gemm_kernel<1, 1><<<dim3(512 / 128, 8192 / 64), 256>>>(
            at, pjw + (size_t)i * 512 * 512, pjb + i * 512, lat, 8192, 512, 512);
    }
}

// round 6
// speedup vs baseline: 1.3967x; 1.0835x over previous
#include <cuda_runtime.h>
#include <cuda_bf16.h>
#include <math.h>
#include <cstdint>

#if defined(__CUDA_ARCH_SPECIFIC__) || defined(__CUDA_ARCH_FEAT_SM103_ALL)
#define HAS_TCGEN05 1
#else
#define HAS_TCGEN05 0
#endif

// ---------------------------------------------------------------------------
// Scratch buffers (packed u32 = bf16 hi << 16 | bf16 lo)
// ---------------------------------------------------------------------------
__device__ uint32_t g_pk_a[15728640];   // ping: x2d/s1/x3d/p1
__device__ uint32_t g_pk_b[50331648];   // pong: s0/p0
__device__ uint32_t g_pk_f[4194304];    // feats packed [512][8192]
__device__ uint8_t  g_wpk[14155776];    // prepacked swizzled conv weight tiles
__device__ uint8_t  g_wpk2[12582912];   // prepacked attention weights (3x qkv + 3x proj)
__device__ uint32_t g_ynpk[8192 * 512]; // layernorm out, packed, token-major
__device__ float    g_qkv[8192 * 1536]; // qkv fp32, token-major
__device__ uint32_t g_atpk[8192 * 512]; // attention out, packed, token-major
__device__ int2     g_dec[8192];
__device__ int      g_ndelta[256];
__device__ int      g_npack[256];

// ---------------------------------------------------------------------------
// Common helpers
// ---------------------------------------------------------------------------
__device__ __forceinline__ uint32_t smem_u32(const void* p) {
    uint32_t a;
    asm("{ .reg .u64 t; cvta.to.shared.u64 t, %1; cvt.u32.u64 %0, t; }"
        : "=r"(a) : "l"(p));
    return a;
}
__device__ __forceinline__ float gelu_tanh(float x) {
    float x3 = x * x * x;
    float t = tanhf(0.7978845608028654f * (x + 0.044715f * x3));
    return 0.5f * x * (1.0f + t);
}
__device__ __forceinline__ uint32_t pack_hl(float f) {
    __nv_bfloat16 h = __float2bfloat16(f);
    __nv_bfloat16 l = __float2bfloat16(f - __bfloat162float(h));
    return ((uint32_t)__bfloat16_as_ushort(h) << 16) | __bfloat16_as_ushort(l);
}
__device__ __forceinline__ float unpack_hl(uint32_t v) {
    float h = __bfloat162float(__ushort_as_bfloat16((unsigned short)(v >> 16)));
    float l = __bfloat162float(__ushort_as_bfloat16((unsigned short)(v & 0xFFFF)));
    return h + l;
}

#if HAS_TCGEN05
__device__ __forceinline__ uint32_t elect_one() {
    uint32_t pred;
    asm volatile("{ .reg .pred p; elect.sync _|p, 0xFFFFFFFF; selp.b32 %0, 1, 0, p; }"
                 : "=r"(pred));
    return pred;
}
#define TCGEN05_ALLOC(a, n) \
    asm volatile("tcgen05.alloc.cta_group::1.sync.aligned.shared::cta.b32 [%0], %1;" \
                 :: "r"((uint32_t)(a)), "r"((uint32_t)(n)) : "memory")
#define TCGEN05_DEALLOC(t, n) \
    asm volatile("tcgen05.dealloc.cta_group::1.sync.aligned.b32 %0, %1;" :: "r"(t), "r"(n))
#define TCGEN05_RELINQ() \
    asm volatile("tcgen05.relinquish_alloc_permit.cta_group::1.sync.aligned;")
#define TCGEN05_COMMIT(m) \
    asm volatile("tcgen05.commit.cta_group::1.mbarrier::arrive::one.shared::cluster.b64 [%0];" \
                 :: "r"((uint32_t)(m)) : "memory")
#define TCGEN05_FENCE_AFTER() \
    asm volatile("tcgen05.fence::after_thread_sync;" ::: "memory")
#define TCGEN05_FENCE_BEFORE() \
    asm volatile("tcgen05.fence::before_thread_sync;" ::: "memory")
#define TCGEN05_WAIT_LD() asm volatile("tcgen05.wait::ld.sync.aligned;" ::: "memory")
#define FENCE_PROXY_ASYNC() asm volatile("fence.proxy.async.shared::cta;" ::: "memory")
#define MBARRIER_INIT(m, c) \
    asm volatile("mbarrier.init.shared.b64 [%0], %1;" :: "r"((uint32_t)(m)), "r"((uint32_t)(c)) : "memory")
#define MBARRIER_INVAL(m) \
    asm volatile("mbarrier.inval.shared.b64 [%0];" :: "r"((uint32_t)(m)) : "memory")
#define MBARRIER_WAIT_PARITY(m, ph) do {                                           \
    uint32_t _m = (uint32_t)(m), _p = (uint32_t)(ph), _d;                          \
    asm volatile("{ .reg .pred p; mbarrier.try_wait.parity.acquire.cta.shared::cta.b64 p, [%1], %2;" \
                 " selp.b32 %0, 1, 0, p; }" : "=r"(_d) : "r"(_m), "r"(_p) : "memory"); \
    if (!_d) {                                                                     \
        asm volatile("{ .reg .pred P1; WL_%=: mbarrier.try_wait.parity.acquire.cta.shared::cta.b64 P1, [%0], %1, 0x989680;" \
                     " @P1 bra.uni WD_%=; bra.uni WL_%=; WD_%=: }"                 \
                     :: "r"(_m), "r"(_p) : "memory");                              \
    }                                                                              \
} while (0)
#define TCGEN05_LD_X32(r, a)                                                       \
    asm volatile("tcgen05.ld.sync.aligned.32x32b.x32.b32 "                         \
        "{%0, %1, %2, %3, %4, %5, %6, %7, %8, %9, %10, %11, %12, %13, %14, %15, "  \
        " %16, %17, %18, %19, %20, %21, %22, %23, %24, %25, %26, %27, %28, %29, %30, %31}, [%32];" \
        : "=r"((r)[0]), "=r"((r)[1]), "=r"((r)[2]), "=r"((r)[3]),                  \
          "=r"((r)[4]), "=r"((r)[5]), "=r"((r)[6]), "=r"((r)[7]),                  \
          "=r"((r)[8]), "=r"((r)[9]), "=r"((r)[10]), "=r"((r)[11]),                \
          "=r"((r)[12]), "=r"((r)[13]), "=r"((r)[14]), "=r"((r)[15]),              \
          "=r"((r)[16]), "=r"((r)[17]), "=r"((r)[18]), "=r"((r)[19]),              \
          "=r"((r)[20]), "=r"((r)[21]), "=r"((r)[22]), "=r"((r)[23]),              \
          "=r"((r)[24]), "=r"((r)[25]), "=r"((r)[26]), "=r"((r)[27]),              \
          "=r"((r)[28]), "=r"((r)[29]), "=r"((r)[30]), "=r"((r)[31])               \
        : "r"(a))

static constexpr uint64_t SMEM_DESC_BASE_SW128 =
    (uint64_t(2) << 61) | (uint64_t(1) << 46) | (uint64_t(64) << 32) | (uint64_t(1) << 16);
__device__ __forceinline__ uint64_t make_desc(uint32_t addr) {
    return SMEM_DESC_BASE_SW128 | ((uint64_t)(addr >> 4) & 0x3FFF);
}
__device__ __forceinline__ void mma_f16_ss(uint32_t d, uint64_t ad, uint64_t bd,
                                           uint32_t idesc, uint32_t en) {
    asm volatile(
        "{ .reg .pred p; setp.ne.u32 p, %5, 0;\n\t"
        "tcgen05.mma.cta_group::1.kind::f16 [%0], %1, %2, %3, {%4, %4, %4, %4}, p; }"
        :: "r"(d), "l"(ad), "l"(bd), "r"(idesc), "r"(0u), "r"(en) : "memory");
}
// idesc: F32 out, BF16 x BF16, N=128, M=128
static constexpr uint32_t CONV_IDESC =
    (1u << 4) | (1u << 7) | (1u << 10) | ((128u / 8) << 17) | ((128u / 16) << 24);
#endif // HAS_TCGEN05

// ---------------------------------------------------------------------------
// Init / pack kernels
// ---------------------------------------------------------------------------
__global__ void conv_decode_kernel(int K, int Kpad, int KV, int KHW, int KW,
                                   int D, int H, int W) {
    int k = blockIdx.x * 256 + threadIdx.x;
    if (k >= Kpad) return;
    if (k < K) {
        int ci = k / KV; int tap = k - ci * KV;
        int kd = tap / KHW; int t2 = tap - kd * KHW;
        int kh = t2 / KW; int kw = t2 - kh * KW;
        g_dec[k] = make_int2(((ci * D + kd) * H + kh) * W + kw,
                             (kd << 20) | (kh << 10) | kw);
    } else {
        g_dec[k] = make_int2(0, 1023 << 20);
    }
}

__global__ void natt_table_kernel() {
    int nb = threadIdx.x;
    if (nb < 245) {
        int od = nb / 49; int r = nb - od * 49;
        int oh = r / 7;   int ow = r - oh * 7;
        g_ndelta[nb] = (od - 2) * 2048 + (oh - 3) * 64 + (ow - 3);
        g_npack[nb]  = (od << 16) | (oh << 8) | ow;
    }
}

__global__ void xpack_kernel(const float* __restrict__ x,
                             uint32_t* __restrict__ dst, int n4) {
    int i = blockIdx.x * 256 + threadIdx.x;
    if (i >= n4) return;
    float4 v = reinterpret_cast<const float4*>(x)[i];
    uint4 o;
    o.x = pack_hl(v.x); o.y = pack_hl(v.y);
    o.z = pack_hl(v.z); o.w = pack_hl(v.w);
    reinterpret_cast<uint4*>(dst)[i] = o;
}

// prepack conv weights ([M][K] layout) into swizzled tiles [bm*NC+kc][hi|lo]
__global__ void wpack_kernel(const float* __restrict__ w, int K, int NC) {
    int kc = blockIdx.x, bm = blockIdx.y;
    int tid = threadIdx.x;
    int r = tid >> 1, half = tid & 1;
    const float* wrow = w + (size_t)(bm * 128 + r) * K;
    uint8_t* hi = g_wpk + (size_t)(bm * NC + kc) * 32768;
    uint8_t* lo = hi + 16384;
#pragma unroll
    for (int i = 0; i < 16; i++) {
        int kk = half * 32 + 2 * i;
        int k = kc * 64 + kk;
        float a0 = (k < K) ? wrow[k] : 0.f;
        float a1 = (k + 1 < K) ? wrow[k + 1] : 0.f;
        uint32_t p0 = pack_hl(a0), p1 = pack_hl(a1);
        uint32_t hp = __byte_perm(p0, p1, 0x7632);
        uint32_t lp = __byte_perm(p0, p1, 0x5410);
        uint32_t off = r * 128 + kk * 2;
        uint32_t sw = off ^ ((off >> 3) & 0x70);
        *reinterpret_cast<uint32_t*>(hi + sw) = hp;
        *reinterpret_cast<uint32_t*>(lo + sw) = lp;
    }
}

// prepack transposed weights ([K][J] layout) into swizzled tiles at dst
__global__ void wpackT_kernel(const float* __restrict__ w, uint8_t* dst,
                              int K, int NC, int J) {
    int kc = blockIdx.x, bm = blockIdx.y;
    int tid = threadIdx.x;
    int r = tid >> 1, half = tid & 1;
    int m = bm * 128 + r;
    uint8_t* hi = dst + (size_t)(bm * NC + kc) * 32768;
    uint8_t* lo = hi + 16384;
#pragma unroll
    for (int i = 0; i < 16; i++) {
        int kk = half * 32 + 2 * i;
        int k = kc * 64 + kk;
        float a0 = (k < K) ? w[(size_t)k * J + m] : 0.f;
        float a1 = (k + 1 < K) ? w[(size_t)(k + 1) * J + m] : 0.f;
        uint32_t p0 = pack_hl(a0), p1 = pack_hl(a1);
        uint32_t hp = __byte_perm(p0, p1, 0x7632);
        uint32_t lp = __byte_perm(p0, p1, 0x5410);
        uint32_t off = r * 128 + kk * 2;
        uint32_t sw = off ^ ((off >> 3) & 0x70);
        *reinterpret_cast<uint32_t*>(hi + sw) = hp;
        *reinterpret_cast<uint32_t*>(lo + sw) = lp;
    }
}

// ---------------------------------------------------------------------------
// Conv kernel (unchanged from R5): tcgen05 MMA, packed gather, prepacked wts.
// ---------------------------------------------------------------------------
struct ConvParams {
    const uint32_t* xpk;
    const float* wf;
    const float* bias;
    uint32_t* outpk;
    float* outf;
    int D, H, W;
    int Hout, Wout;
    int sd, sh, sw, pd, ph, pw;
    int K, NC;
    int outStrideC, outOffset;
    int gelu;
};

#define CONV_SMEM_BYTES (1024 + 8 * 16384 + 64)

__global__ __launch_bounds__(512) void conv_mma_kernel(ConvParams p) {
    extern __shared__ char smem_raw[];
    char* smem_al = (char*)(((uintptr_t)smem_raw + 1023) & ~(uintptr_t)1023);

    const int tid = threadIdx.x;
    const int bn = blockIdx.x, bm = blockIdx.y;
    const int m_base = bm * 128;
    const int HWo = p.Hout * p.Wout;

#if HAS_TCGEN05
    const uint32_t sb = smem_u32(smem_al);
    const uint32_t mbar = sb + 131072;
    const uint32_t tmem_slot = sb + 131080;
    const int wid = tid >> 5;
    const int lane = tid & 31;

    if (wid == 0) {
        TCGEN05_ALLOC(tmem_slot, 128);
        TCGEN05_RELINQ();
    }
    if (tid == 0) MBARRIER_INIT(mbar, 1);
    __syncthreads();
    uint32_t tmem;
    asm volatile("ld.shared.b32 %0, [%1];" : "=r"(tmem) : "r"(tmem_slot));

    const int r = tid >> 2;
    const int q = tid & 3;
    const int n = bn * 128 + r;
    const int od = n / HWo; int rr2 = n - od * HWo;
    const int oh = rr2 / p.Wout; const int ow = rr2 - oh * p.Wout;
    const int id0 = od * p.sd - p.pd;
    const int ih0 = oh * p.sh - p.ph;
    const int iw0 = ow * p.sw - p.pw;
    const int gbase = (id0 * p.H + ih0) * p.W + iw0;
    const uint8_t* wsrc_base = g_wpk + (size_t)bm * p.NC * 32768;
    const int NC = p.NC;

    auto fill = [&](int st, int kc) {
        char* stage = smem_al + st * 65536;
        {
            const uint8_t* src = wsrc_base + (size_t)kc * 32768 + tid * 16;
            char* dst = stage + tid * 16;
#pragma unroll
            for (int i = 0; i < 4; i++) {
                uint4 v = *reinterpret_cast<const uint4*>(src + i * 8192);
                *reinterpret_cast<uint4*>(dst + i * 8192) = v;
            }
        }
        char* Bhi = stage + 32768;
        char* Blo = stage + 49152;
        const int kt = kc * 64;
#pragma unroll
        for (int i = 0; i < 8; i++) {
            int kk = q * 16 + 2 * i;
            int k = kt + kk;
            int4 dv = *reinterpret_cast<const int4*>(&g_dec[k]);
            uint32_t v0 = 0, v1 = 0;
            {
                int kd = dv.y >> 20, kh = (dv.y >> 10) & 1023, kw = dv.y & 1023;
                if ((unsigned)(id0 + kd) < (unsigned)p.D &&
                    (unsigned)(ih0 + kh) < (unsigned)p.H &&
                    (unsigned)(iw0 + kw) < (unsigned)p.W)
                    v0 = p.xpk[gbase + dv.x];
            }
            {
                int kd = dv.w >> 20, kh = (dv.w >> 10) & 1023, kw = dv.w & 1023;
                if ((unsigned)(id0 + kd) < (unsigned)p.D &&
                    (unsigned)(ih0 + kh) < (unsigned)p.H &&
                    (unsigned)(iw0 + kw) < (unsigned)p.W)
                    v1 = p.xpk[gbase + dv.z];
            }
            uint32_t off = r * 128 + kk * 2;
            uint32_t sw = off ^ ((off >> 3) & 0x70);
            *reinterpret_cast<uint32_t*>(Bhi + sw) = __byte_perm(v0, v1, 0x7632);
            *reinterpret_cast<uint32_t*>(Blo + sw) = __byte_perm(v0, v1, 0x5410);
        }
    };

    fill(0, 0);
    FENCE_PROXY_ASYNC();
    __syncthreads();

    int wpar = 0;
    uint32_t first = 0;

    for (int kc = 0; kc < NC; kc++) {
        int st = kc & 1;
        if (wid == 0 && elect_one()) {
            uint32_t stb = sb + st * 65536;
            uint64_t dAh = make_desc(stb);
            uint64_t dAl = make_desc(stb + 16384);
            uint64_t dBh = make_desc(stb + 32768);
            uint64_t dBl = make_desc(stb + 49152);
#pragma unroll
            for (int s = 0; s < 4; s++) {
                uint64_t o = s * 2;
                mma_f16_ss(tmem, dAh + o, dBh + o, CONV_IDESC, first); first = 1;
                mma_f16_ss(tmem, dAh + o, dBl + o, CONV_IDESC, 1);
                mma_f16_ss(tmem, dAl + o, dBh + o, CONV_IDESC, 1);
            }
            TCGEN05_COMMIT(mbar);
        }
        if (kc + 1 < NC) {
            if (kc >= 1) { MBARRIER_WAIT_PARITY(mbar, wpar & 1); wpar++; }
            fill((kc + 1) & 1, kc + 1);
            FENCE_PROXY_ASYNC();
            __syncthreads();
        }
    }
    while (wpar < NC) { MBARRIER_WAIT_PARITY(mbar, wpar & 1); wpar++; }
    TCGEN05_FENCE_AFTER();

    {
        const int sp = wid & 3;
        const int cb = wid >> 2;
        const int m = m_base + sp * 32 + lane;
        const float bv = p.bias[m];
        uint32_t dr[32];
        TCGEN05_LD_X32(dr, tmem + cb * 32);
        TCGEN05_WAIT_LD();
        size_t obase = (size_t)m * p.outStrideC + p.outOffset + bn * 128 + cb * 32;
        if (p.outpk) {
            uint32_t* orow = p.outpk + obase;
#pragma unroll
            for (int j = 0; j < 32; j++) {
                float v = __uint_as_float(dr[j]) + bv;
                if (p.gelu) v = gelu_tanh(v);
                orow[j] = pack_hl(v);
            }
        } else {
            float* orow = p.outf + obase;
#pragma unroll
            for (int j = 0; j < 32; j++) {
                float v = __uint_as_float(dr[j]) + bv;
                if (p.gelu) v = gelu_tanh(v);
                orow[j] = v;
            }
        }
        TCGEN05_FENCE_BEFORE();
    }
    __syncthreads();
    if (tid == 0) MBARRIER_INVAL(mbar);
    if (wid == 0) TCGEN05_DEALLOC(tmem, 128);

#else  // FFMA fallback (never executes on GB300)
    const int tx = tid & 15, ty = tid >> 4;
    const int n0 = bn * 128 + tx * 8;
    float acc[4][8];
#pragma unroll
    for (int i = 0; i < 4; i++)
#pragma unroll
        for (int j = 0; j < 8; j++) acc[i][j] = 0.f;
    int id0s[8], ih0s[8], iw0s[8], gb[8];
    for (int j = 0; j < 8; j++) {
        int n = n0 + j;
        int od = n / HWo; int rr2 = n - od * HWo;
        int oh = rr2 / p.Wout; int ow = rr2 - oh * p.Wout;
        id0s[j] = od * p.sd - p.pd;
        ih0s[j] = oh * p.sh - p.ph;
        iw0s[j] = ow * p.sw - p.pw;
        gb[j] = (id0s[j] * p.H + ih0s[j]) * p.W + iw0s[j];
    }
    for (int k = 0; k < p.K; k++) {
        int2 dv = g_dec[k];
        int kd = dv.y >> 20, kh = (dv.y >> 10) & 1023, kw = dv.y & 1023;
        float b[8];
        for (int j = 0; j < 8; j++) {
            b[j] = 0.f;
            if ((unsigned)(id0s[j] + kd) < (unsigned)p.D &&
                (unsigned)(ih0s[j] + kh) < (unsigned)p.H &&
                (unsigned)(iw0s[j] + kw) < (unsigned)p.W)
                b[j] = unpack_hl(p.xpk[gb[j] + dv.x]);
        }
        for (int i = 0; i < 4; i++) {
            float a = p.wf[(size_t)(m_base + ty * 4 + i) * p.K + k];
            for (int j = 0; j < 8; j++) acc[i][j] = fmaf(a, b[j], acc[i][j]);
        }
    }
    for (int i = 0; i < 4; i++) {
        int m = m_base + ty * 4 + i;
        float bvl = p.bias[m];
        size_t obase = (size_t)m * p.outStrideC + p.outOffset + n0;
        for (int j = 0; j < 8; j++) {
            float v = acc[i][j] + bvl;
            if (p.gelu) v = gelu_tanh(v);
            if (p.outpk) p.outpk[obase + j] = pack_hl(v);
            else p.outf[obase + j] = v;
        }
    }
#endif
}

// ---------------------------------------------------------------------------
// Token GEMM on tcgen05: C[t,j] = sum_k B[t,k] * W[k,j] (+bias)
// A = prepacked weights (wpk), B = packed activations token-major [T x Kdim].
// MODE 0: store fp32 token-major C[t*J + j] = v + bias[j]      (qkv)
// MODE 1: residual fp32 channel-major C[j*T + t] += v + bias[j] (proj)
// Grid: (T/128, J/128). Block 512.
// ---------------------------------------------------------------------------
struct TokParams {
    const uint32_t* bpk;      // packed activations [T][Kdim]
    const uint8_t* wpk;       // prepacked weight tiles
    const float* wf;          // fp32 weights [Kdim][J] (fallback only)
    const float* bias;
    float* out;
    int T, J, Kdim, NC, mode;
};

__global__ __launch_bounds__(512) void tok_mma_kernel(TokParams p) {
    extern __shared__ char smem_raw[];
    char* smem_al = (char*)(((uintptr_t)smem_raw + 1023) & ~(uintptr_t)1023);

    const int tid = threadIdx.x;
    const int bn = blockIdx.x, bm = blockIdx.y;
    const int m_base = bm * 128;

#if HAS_TCGEN05
    const uint32_t sb = smem_u32(smem_al);
    const uint32_t mbar = sb + 131072;
    const uint32_t tmem_slot = sb + 131080;
    const int wid = tid >> 5;
    const int lane = tid & 31;

    if (wid == 0) {
        TCGEN05_ALLOC(tmem_slot, 128);
        TCGEN05_RELINQ();
    }
    if (tid == 0) MBARRIER_INIT(mbar, 1);
    __syncthreads();
    uint32_t tmem;
    asm volatile("ld.shared.b32 %0, [%1];" : "=r"(tmem) : "r"(tmem_slot));

    const int r = tid >> 2;          // token row 0..127
    const int q = tid & 3;           // k-quarter (16 k each)
    const uint32_t* bsrc = p.bpk + (size_t)(bn * 128 + r) * p.Kdim;
    const uint8_t* wsrc_base = p.wpk + (size_t)bm * p.NC * 32768;
    const int NC = p.NC;

    auto fill = [&](int st, int kc) {
        char* stage = smem_al + st * 65536;
        {
            const uint8_t* src = wsrc_base + (size_t)kc * 32768 + tid * 16;
            char* dst = stage + tid * 16;
#pragma unroll
            for (int i = 0; i < 4; i++) {
                uint4 v = *reinterpret_cast<const uint4*>(src + i * 8192);
                *reinterpret_cast<uint4*>(dst + i * 8192) = v;
            }
        }
        char* Bhi = stage + 32768;
        char* Blo = stage + 49152;
        const uint32_t* src = bsrc + kc * 64 + q * 16;
        uint32_t buf[16];
#pragma unroll
        for (int i = 0; i < 4; i++)
            *reinterpret_cast<uint4*>(&buf[i * 4]) =
                *reinterpret_cast<const uint4*>(src + i * 4);
#pragma unroll
        for (int i = 0; i < 8; i++) {
            int kk = q * 16 + 2 * i;
            uint32_t v0 = buf[2 * i], v1 = buf[2 * i + 1];
            uint32_t off = r * 128 + kk * 2;
            uint32_t sw = off ^ ((off >> 3) & 0x70);
            *reinterpret_cast<uint32_t*>(Bhi + sw) = __byte_perm(v0, v1, 0x7632);
            *reinterpret_cast<uint32_t*>(Blo + sw) = __byte_perm(v0, v1, 0x5410);
        }
    };

    fill(0, 0);
    FENCE_PROXY_ASYNC();
    __syncthreads();

    int wpar = 0;
    uint32_t first = 0;

    for (int kc = 0; kc < NC; kc++) {
        int st = kc & 1;
        if (wid == 0 && elect_one()) {
            uint32_t stb = sb + st * 65536;
            uint64_t dAh = make_desc(stb);
            uint64_t dAl = make_desc(stb + 16384);
            uint64_t dBh = make_desc(stb + 32768);
            uint64_t dBl = make_desc(stb + 49152);
#pragma unroll
            for (int s = 0; s < 4; s++) {
                uint64_t o = s * 2;
                mma_f16_ss(tmem, dAh + o, dBh + o, CONV_IDESC, first); first = 1;
                mma_f16_ss(tmem, dAh + o, dBl + o, CONV_IDESC, 1);
                mma_f16_ss(tmem, dAl + o, dBh + o, CONV_IDESC, 1);
            }
            TCGEN05_COMMIT(mbar);
        }
        if (kc + 1 < NC) {
            if (kc >= 1) { MBARRIER_WAIT_PARITY(mbar, wpar & 1); wpar++; }
            fill((kc + 1) & 1, kc + 1);
            FENCE_PROXY_ASYNC();
            __syncthreads();
        }
    }
    while (wpar < NC) { MBARRIER_WAIT_PARITY(mbar, wpar & 1); wpar++; }
    TCGEN05_FENCE_AFTER();

    {
        const int sp = wid & 3;
        const int cb = wid >> 2;
        const int m = m_base + sp * 32 + lane;
        const float bv = p.bias[m];
        const int t0 = bn * 128 + cb * 32;
        uint32_t dr[32];
        TCGEN05_LD_X32(dr, tmem + cb * 32);
        TCGEN05_WAIT_LD();
        if (p.mode == 0) {
#pragma unroll
            for (int j = 0; j < 32; j++)
                p.out[(size_t)(t0 + j) * p.J + m] = __uint_as_float(dr[j]) + bv;
        } else {
            float* orow = p.out + (size_t)m * p.T + t0;
#pragma unroll
            for (int j = 0; j < 8; j++) {
                float4* cp = reinterpret_cast<float4*>(orow + j * 4);
                float4 o = *cp;
                o.x += __uint_as_float(dr[j * 4 + 0]) + bv;
                o.y += __uint_as_float(dr[j * 4 + 1]) + bv;
                o.z += __uint_as_float(dr[j * 4 + 2]) + bv;
                o.w += __uint_as_float(dr[j * 4 + 3]) + bv;
                *cp = o;
            }
        }
        TCGEN05_FENCE_BEFORE();
    }
    __syncthreads();
    if (tid == 0) MBARRIER_INVAL(mbar);
    if (wid == 0) TCGEN05_DEALLOC(tmem, 128);

#else  // FFMA fallback (never executes on GB300)
    for (int idx = tid; idx < 128 * 128; idx += 512) {
        int tl = idx >> 7, jl = idx & 127;
        int t = bn * 128 + tl, j = m_base + jl;
        float s = 0.f;
        for (int k = 0; k < p.Kdim; k++)
            s += unpack_hl(p.bpk[(size_t)t * p.Kdim + k]) * p.wf[(size_t)k * p.J + j];
        s += p.bias[j];
        if (p.mode == 0) p.out[(size_t)t * p.J + j] = s;
        else p.out[(size_t)j * p.T + t] += s;
    }
#endif
}

// ---------------------------------------------------------------------------
// LayerNorm: fp32 channel-major in -> packed u32 token-major out
// ---------------------------------------------------------------------------
__global__ __launch_bounds__(256) void layernorm_kernel(
    const float* __restrict__ x, const float* __restrict__ g,
    const float* __restrict__ b, uint32_t* __restrict__ ypk, int T) {
    const int tx = threadIdx.x;
    const int ty = threadIdx.y;
    const int t = blockIdx.x * 32 + tx;

    float s = 0.f, ss = 0.f;
#pragma unroll
    for (int i = 0; i < 64; i++) {
        int c = ty * 64 + i;
        float v = x[(size_t)c * T + t];
        s += v; ss += v * v;
    }
    __shared__ float shs[8][32], shss[8][32];
    __shared__ float smu[32], srs[32];
    shs[ty][tx] = s; shss[ty][tx] = ss;
    __syncthreads();
    if (ty == 0) {
        float S = 0.f, SS = 0.f;
#pragma unroll
        for (int j = 0; j < 8; j++) { S += shs[j][tx]; SS += shss[j][tx]; }
        float mu = S * (1.f / 512.f);
        float var = SS * (1.f / 512.f) - mu * mu;
        smu[tx] = mu;
        srs[tx] = rsqrtf(var + 1e-5f);
    }
    __syncthreads();
    float mu = smu[tx], rs = srs[tx];
    uint32_t* yrow = ypk + (size_t)t * 512 + ty * 64;
#pragma unroll
    for (int i = 0; i < 64; i++) {
        int c = ty * 64 + i;
        float v = x[(size_t)c * T + t];
        yrow[i] = pack_hl((v - mu) * rs * g[c] + b[c]);
    }
}

// ---------------------------------------------------------------------------
// Neighborhood attention: qkv fp32 token-major -> packed u32 token-major
// ---------------------------------------------------------------------------
__global__ __launch_bounds__(256) void natt_kernel(
    const float* __restrict__ qkv, uint32_t* __restrict__ atpk) {
    const int warp = threadIdx.x >> 5;
    const int lane = threadIdx.x & 31;
    const int t = blockIdx.x * 8 + warp;
    const int head = blockIdx.y;
    const int d = t >> 11;
    const int hh = (t >> 6) & 31;
    const int ww = t & 63;

    __shared__ float qsh[8][64];
    __shared__ float psh[8][248];
    const float* qp = qkv + (size_t)t * 1536 + head * 64;
    qsh[warp][lane] = qp[lane] * 0.125f;
    qsh[warp][lane + 32] = qp[lane + 32] * 0.125f;
    __syncwarp();

    float sc[8];
    float m = -1e30f;
#pragma unroll
    for (int it = 0; it < 8; it++) {
        int nb = it * 32 + lane;
        float dot = -1e30f;
        if (nb < 245) {
            int pk = g_npack[nb];
            int nd = d + (pk >> 16) - 2;
            int nh = hh + ((pk >> 8) & 255) - 3;
            int nw = ww + (pk & 255) - 3;
            if ((unsigned)nd < 4u && (unsigned)nh < 32u && (unsigned)nw < 64u) {
                int nt = t + g_ndelta[nb];
                const float4* kp = reinterpret_cast<const float4*>(
                    qkv + (size_t)nt * 1536 + 512 + head * 64);
                float s = 0.f;
#pragma unroll
                for (int q4 = 0; q4 < 16; q4++) {
                    float4 kv = kp[q4];
                    s = fmaf(qsh[warp][q4 * 4 + 0], kv.x, s);
                    s = fmaf(qsh[warp][q4 * 4 + 1], kv.y, s);
                    s = fmaf(qsh[warp][q4 * 4 + 2], kv.z, s);
                    s = fmaf(qsh[warp][q4 * 4 + 3], kv.w, s);
                }
                dot = s;
            }
        }
        sc[it] = dot;
        m = fmaxf(m, dot);
    }
#pragma unroll
    for (int o = 16; o; o >>= 1) m = fmaxf(m, __shfl_xor_sync(0xffffffffu, m, o));

    float l = 0.f;
#pragma unroll
    for (int it = 0; it < 8; it++) {
        int nb = it * 32 + lane;
        float e = (sc[it] > -1e29f) ? __expf(sc[it] - m) : 0.f;
        if (nb < 248) psh[warp][nb] = e;
        l += e;
    }
#pragma unroll
    for (int o = 16; o; o >>= 1) l += __shfl_xor_sync(0xffffffffu, l, o);
    __syncwarp();

    float acc0 = 0.f, acc1 = 0.f;
    for (int nb = 0; nb < 245; nb++) {
        float pb = psh[warp][nb];
        if (pb > 0.f) {
            int nt = t + g_ndelta[nb];
            const float* vp = qkv + (size_t)nt * 1536 + 1024 + head * 64;
            acc0 = fmaf(pb, vp[lane], acc0);
            acc1 = fmaf(pb, vp[lane + 32], acc1);
        }
    }
    float inv = 1.f / l;
    uint32_t* op = atpk + (size_t)t * 512 + head * 64;
    op[lane] = pack_hl(acc0 * inv);
    op[lane + 32] = pack_hl(acc1 * inv);
}

// ---------------------------------------------------------------------------
// Host launcher
// ---------------------------------------------------------------------------
extern "C" void kernel_launch(void* const* d_in, const int* in_sizes, int n_in,
                              void* d_out, int out_size) {
    const float* x2d  = (const float*)d_in[0];
    const float* x3d  = (const float*)d_in[1];
    const float* sw0  = (const float*)d_in[2];  const float* sb0 = (const float*)d_in[3];
    const float* sw1  = (const float*)d_in[4];  const float* sb1 = (const float*)d_in[5];
    const float* sw2  = (const float*)d_in[6];  const float* sb2 = (const float*)d_in[7];
    const float* pw0  = (const float*)d_in[8];  const float* pb0 = (const float*)d_in[9];
    const float* pw1  = (const float*)d_in[10]; const float* pb1 = (const float*)d_in[11];
    const float* pw2  = (const float*)d_in[12]; const float* pb2 = (const float*)d_in[13];
    const float* latw = (const float*)d_in[14]; const float* latb = (const float*)d_in[15];
    const float* lng  = (const float*)d_in[16]; const float* lnb  = (const float*)d_in[17];
    const float* qkvw = (const float*)d_in[18]; const float* qkvb = (const float*)d_in[19];
    const float* pjw  = (const float*)d_in[20]; const float* pjb  = (const float*)d_in[21];
    float* lat = (float*)d_out;

    uint32_t *pkA, *pkB, *pkF, *ynpk, *atpk;
    float *qkvB;
    uint8_t *wpk2;
    cudaGetSymbolAddress((void**)&pkA, g_pk_a);
    cudaGetSymbolAddress((void**)&pkB, g_pk_b);
    cudaGetSymbolAddress((void**)&pkF, g_pk_f);
    cudaGetSymbolAddress((void**)&ynpk, g_ynpk);
    cudaGetSymbolAddress((void**)&qkvB, g_qkv);
    cudaGetSymbolAddress((void**)&atpk, g_atpk);
    cudaGetSymbolAddress((void**)&wpk2, g_wpk2);

    cudaFuncSetAttribute(conv_mma_kernel,
                         cudaFuncAttributeMaxDynamicSharedMemorySize, CONV_SMEM_BYTES);
    cudaFuncSetAttribute(tok_mma_kernel,
                         cudaFuncAttributeMaxDynamicSharedMemorySize, CONV_SMEM_BYTES);

    natt_table_kernel<<<1, 256>>>();

    // prepack attention weights once (qkv: NC=8 bm=12 -> 3MB; proj: NC=8 bm=4 -> 1MB)
    const size_t QKV_PK = 8 * 12 * 32768;   // 3145728
    const size_t PRJ_PK = 8 * 4 * 32768;    // 1048576
    for (int i = 0; i < 3; i++) {
        wpackT_kernel<<<dim3(8, 12), 256>>>(qkvw + (size_t)i * 512 * 1536,
                                            wpk2 + i * QKV_PK, 512, 8, 1536);
        wpackT_kernel<<<dim3(8, 4), 256>>>(pjw + (size_t)i * 512 * 512,
                                           wpk2 + 3 * QKV_PK + i * PRJ_PK, 512, 8, 512);
    }

    auto run_conv = [&](const uint32_t* xpk, const float* wf, const float* bias,
                        uint32_t* outpk, float* outf,
                        int Cin, int D, int H, int W, int Dout, int Hout, int Wout,
                        int KD, int KH, int KW, int sd, int sh, int sw,
                        int pd, int ph, int pw, int Cout,
                        int outStrideC, int outOffset, int gelu) {
        int K = Cin * KD * KH * KW;
        int NC = (K + 63) / 64;
        int Kp = NC * 64;
        conv_decode_kernel<<<(Kp + 255) / 256, 256>>>(K, Kp, KD * KH * KW, KH * KW,
                                                      KW, D, H, W);
        wpack_kernel<<<dim3(NC, Cout / 128), 256>>>(wf, K, NC);
        int Nvox = Dout * Hout * Wout;
        ConvParams p{ xpk, wf, bias, outpk, outf,
                      D, H, W, Hout, Wout, sd, sh, sw, pd, ph, pw,
                      K, NC, outStrideC, outOffset, gelu };
        conv_mma_kernel<<<dim3(Nvox / 128, Cout / 128), 512, CONV_SMEM_BYTES>>>(p);
    };

    // ---- 2D tower ----
    xpack_kernel<<<(8 * 256 * 512 / 4 + 255) / 256, 256>>>(x2d, pkA, 8 * 256 * 512 / 4);
    run_conv(pkA, sw0, sb0, pkB, nullptr, 8, 1, 256, 512, 1, 128, 256,
             1, 3, 3, 1, 2, 2, 0, 1, 1, 128, 32768, 0, 1);
    run_conv(pkB, sw1, sb1, pkA, nullptr, 128, 1, 128, 256, 1, 64, 128,
             1, 3, 3, 1, 2, 2, 0, 1, 1, 256, 8192, 0, 1);
    run_conv(pkA, sw2, sb2, pkF, nullptr, 256, 1, 64, 128, 1, 32, 64,
             1, 3, 3, 1, 2, 2, 0, 1, 1, 512, 8192, 3 * 2048, 1);

    // ---- 3D tower ----
    xpack_kernel<<<(5 * 24 * 256 * 512 / 4 + 255) / 256, 256>>>(
        x3d, pkA, 5 * 24 * 256 * 512 / 4);
    run_conv(pkA, pw0, pb0, pkB, nullptr, 5, 24, 256, 512, 12, 128, 256,
             3, 3, 3, 2, 2, 2, 1, 1, 1, 128, 393216, 0, 1);
    run_conv(pkB, pw1, pb1, pkA, nullptr, 128, 12, 128, 256, 6, 64, 128,
             3, 3, 3, 2, 2, 2, 1, 1, 1, 256, 49152, 0, 1);
    run_conv(pkA, pw2, pb2, pkF, nullptr, 256, 6, 64, 128, 3, 32, 64,
             3, 3, 3, 2, 2, 2, 1, 1, 1, 512, 8192, 0, 1);

    // ---- lateral 1x1x1 -> d_out fp32 ----
    run_conv(pkF, latw, latb, nullptr, lat, 512, 4, 32, 64, 4, 32, 64,
             1, 1, 1, 1, 1, 1, 0, 0, 0, 512, 8192, 0, 0);

    // ---- 3 neighborhood-attention blocks ----
    for (int i = 0; i < 3; i++) {
        layernorm_kernel<<<8192 / 32, dim3(32, 8)>>>(lat, lng + i * 512, lnb + i * 512,
                                                     ynpk, 8192);
        TokParams pq{ ynpk, wpk2 + i * QKV_PK, qkvw + (size_t)i * 512 * 1536,
                      qkvb + i * 1536, qkvB, 8192, 1536, 512, 8, 0 };
        tok_mma_kernel<<<dim3(8192 / 128, 1536 / 128), 512, CONV_SMEM_BYTES>>>(pq);
        natt_kernel<<<dim3(8192 / 8, 8), 256>>>(qkvB, atpk);
        TokParams pp{ atpk, wpk2 + 3 * QKV_PK + i * PRJ_PK,
                      pjw + (size_t)i * 512 * 512,
                      pjb + i * 512, lat, 8192, 512, 512, 8, 1 };
        tok_mma_kernel<<<dim3(8192 / 128, 512 / 128), 512, CONV_SMEM_BYTES>>>(pp);
    }
}